// round 6
// baseline (speedup 1.0000x reference)
#include <cuda_runtime.h>
#include <cuda_bf16.h>
#include <float.h>
#include <math.h>
#include <stdint.h>

#define HW 16384
#define Dm 256
#define Bm 4
#define NBLK 128

// ---------------- scratch ----------------------------------------------------
__device__ float g_x[Bm * HW * Dm];     // GEMM1 output, layout [b][n][d]
__device__ float g_proj[Bm * HW * Dm];  // GEMM2 output, layout [b][n][e]
__device__ float g_s[Dm];
__device__ float g_c[Dm];
__device__ unsigned char g_m1[Bm * HW];
__device__ unsigned char g_m0[Bm * HW];
__device__ float g_ps[Dm * 512];
__device__ float g_pq[Dm * 512];
__device__ float g_pfg[Bm * Dm * NBLK];
__device__ float g_pbg[Bm * Dm * NBLK];
__device__ float g_mfg[Bm * Dm];
__device__ float g_mbg[Bm * Dm];
__device__ float g_bl[8];
__device__ int g_inc[8];

// ---------------- block reduction --------------------------------------------
__device__ __forceinline__ float blk_sum(volatile float* scratch, float v, int tid) {
    int lane = tid & 31, w = tid >> 5;
#pragma unroll
    for (int off = 16; off; off >>= 1) v += __shfl_down_sync(0xffffffffu, v, off);
    if (lane == 0) scratch[w] = v;
    __syncthreads();
    if (w == 0) {
        v = (lane < 8) ? scratch[lane] : 0.f;
#pragma unroll
        for (int off = 4; off; off >>= 1) v += __shfl_down_sync(0xffffffffu, v, off);
        if (lane == 0) scratch[32] = v;
    }
    __syncthreads();
    return scratch[32];
}

// ---------------- masks ------------------------------------------------------
__global__ void k_masks(const float* __restrict__ prob_ori, const float* __restrict__ prob_aug,
                        const float* __restrict__ unc, const int* __restrict__ labels) {
    int idx = blockIdx.x * blockDim.x + threadIdx.x;
    if (idx >= Bm * HW) return;
    int b = idx >> 14;
    int hw = idx & (HW - 1);
    const float* po = prob_ori + (size_t)b * 2 * HW;
    const float* pa = prob_aug + (size_t)b * 2 * HW;
    int io = po[HW + hw] > po[hw];
    int ia = pa[HW + hw] > pa[hw];
    bool rel = (io == ia);
    bool diff = unc[idx] > 0.5f;
    int lab = labels[idx];
    bool valid = rel && diff;
    g_m1[idx] = (unsigned char)(valid && lab == 1);
    g_m0[idx] = (unsigned char)(valid && lab == 0);
}

// ---------------- bf16 hi/lo split -------------------------------------------
__device__ __forceinline__ void split2(float a, float b, uint32_t& h, uint32_t& l) {
    __nv_bfloat16 ah = __float2bfloat16_rn(a), bh = __float2bfloat16_rn(b);
    float ar = a - __bfloat162float(ah), br = b - __bfloat162float(bh);
    __nv_bfloat16 al = __float2bfloat16_rn(ar), bl = __float2bfloat16_rn(br);
    h = (uint32_t)*(unsigned short*)&ah | ((uint32_t)*(unsigned short*)&bh << 16);
    l = (uint32_t)*(unsigned short*)&al | ((uint32_t)*(unsigned short*)&bl << 16);
}

__device__ __forceinline__ void mma16816(float* c, const uint32_t* a, uint32_t b0, uint32_t b1) {
    asm volatile(
        "mma.sync.aligned.m16n8k16.row.col.f32.bf16.bf16.f32 "
        "{%0,%1,%2,%3}, {%4,%5,%6,%7}, {%8,%9}, {%0,%1,%2,%3};"
        : "+f"(c[0]), "+f"(c[1]), "+f"(c[2]), "+f"(c[3])
        : "r"(a[0]), "r"(a[1]), "r"(a[2]), "r"(a[3]), "r"(b0), "r"(b1));
}

#define CP16(dst_u32, src_ptr) \
    asm volatile("cp.async.cg.shared.global [%0], [%1], 16;" ::"r"(dst_u32), "l"(src_ptr))
#define CP_COMMIT() asm volatile("cp.async.commit_group;" ::: "memory")
#define CP_WAIT1() asm volatile("cp.async.wait_group 1;" ::: "memory")
#define CP_WAIT0() asm volatile("cp.async.wait_group 0;" ::: "memory")

// ---------------- HMMA GEMM: C[e,n] = sum_d A[e,d]*B[n,d] + bias[e] ----------
// cp.async double-buffered raw staging -> convert -> single-stage bf16 tiles.
// APPLY=false: B = feat[b][d][n] (transposed), C -> g_x[b][n][e], BN partials.
// APPLY=true:  B = relu(bn(g_x[b][n][d])), C -> g_proj[b][n][e], proto partials.
#define ROWW 36                 // bf16 tile: words per padded row
#define MATW (128 * ROWW)       // 4608 words per bf16 matrix
#define RAWA_ROWW 68            // raw A tile [128][64f +4 pad]
#define RAWB1_ROWW 132          // raw B tile GEMM1 [64][128f +4 pad]
#define RAWB2_ROWW 68           // raw B tile GEMM2 [128][64f +4 pad]
#define RAW_STAGE 8704          // words per raw stage (max of both shapes)
#define OFF_RAWA (4 * MATW)                 // 18432
#define OFF_RAWB (OFF_RAWA + 2 * RAW_STAGE) // 35840
#define OFF_EXT (OFF_RAWB + 2 * RAW_STAGE)  // 53248
#define GEMM_SMEM ((OFF_EXT + 1920) * 4)    // 220672 bytes

template <bool APPLY>
__global__ __launch_bounds__(256, 1) void k_gemm_mma(const float* __restrict__ Asrc,
                                                     const float* __restrict__ Wm,
                                                     const float* __restrict__ bias) {
    extern __shared__ __align__(16) char smraw[];
    uint32_t* Ah = (uint32_t*)smraw;
    uint32_t* Al = Ah + MATW;
    uint32_t* Bh = Al + MATW;
    uint32_t* Bl = Bh + MATW;
    float* fbase = (float*)smraw;
    float* ext = fbase + OFF_EXT;
    float* bsm = ext;             // [128]
    float* m1f = ext + 128;       // [128]
    float* m0f = ext + 256;       // [128]
    float* scs = ext + 384;       // [256]
    float* scc = ext + 640;       // [256]
    float* red = ext + 896;       // [2][128][4]
    const uint32_t sb = (uint32_t)__cvta_generic_to_shared(smraw);

    const int tid = threadIdx.x, lane = tid & 31, wid = tid >> 5;
    const int warp_m = wid >> 2, warp_n = wid & 3;
    const int bx = blockIdx.x, mb = blockIdx.y, bb = blockIdx.z;
    const int nb = bx * 128;

    if (tid < 128) bsm[tid] = bias[mb * 128 + tid];
    if (APPLY) {
        scs[tid] = g_s[tid];
        scc[tid] = g_c[tid];
        if (tid < 128) {
            m1f[tid] = (float)g_m1[bb * HW + nb + tid];
            m0f[tid] = (float)g_m0[bb * HW + nb + tid];
        }
    }

    const float* Wbase = Wm + (size_t)(mb * 128) * 256;
    const float* featb = Asrc + (size_t)bb * Dm * HW;  // [d][n]
    const float* gxb = g_x + (size_t)bb * HW * 256;    // [n][d]

    float acc[4][4][4];
#pragma unroll
    for (int i = 0; i < 4; i++)
#pragma unroll
        for (int j = 0; j < 4; j++)
#pragma unroll
            for (int k = 0; k < 4; k++) acc[i][j][k] = 0.f;

    const int rA = lane >> 2, cA = lane & 3;

    // ---- issue cp.async for one chunk ----
    auto issue = [&](int kc, int stage) {
        const int d0 = kc * 64;
        uint32_t rawA = sb + (OFF_RAWA + stage * RAW_STAGE) * 4;
        uint32_t rawB = sb + (OFF_RAWB + stage * RAW_STAGE) * 4;
#pragma unroll
        for (int it = 0; it < 8; it++) {
            int lin = it * 256 + tid;
            int row = lin >> 4, c = lin & 15;
            CP16(rawA + (row * RAWA_ROWW + c * 4) * 4, Wbase + (size_t)row * 256 + d0 + c * 4);
        }
        if (!APPLY) {
#pragma unroll
            for (int it = 0; it < 8; it++) {
                int lin = it * 256 + tid;
                int row = lin >> 5, c = lin & 31;
                CP16(rawB + (row * RAWB1_ROWW + c * 4) * 4,
                     featb + (size_t)(d0 + row) * HW + nb + c * 4);
            }
        } else {
#pragma unroll
            for (int it = 0; it < 8; it++) {
                int lin = it * 256 + tid;
                int row = lin >> 4, c = lin & 15;
                CP16(rawB + (row * RAWB2_ROWW + c * 4) * 4,
                     gxb + (size_t)(nb + row) * 256 + d0 + c * 4);
            }
        }
        CP_COMMIT();
    };

    issue(0, 0);

#pragma unroll 1
    for (int kc = 0; kc < 4; kc++) {
        const int stage = kc & 1;
        const int d0 = kc * 64;
        if (kc < 3) issue(kc + 1, stage ^ 1);
        if (kc < 3) CP_WAIT1(); else CP_WAIT0();
        __syncthreads();  // raw ready + all warps done with previous bf16 tiles

        const float* rawAf = fbase + OFF_RAWA + stage * RAW_STAGE;
        const float* rawBf = fbase + OFF_RAWB + stage * RAW_STAGE;

        // ---- convert A (128x64) ----
#pragma unroll
        for (int it = 0; it < 8; it++) {
            int idx = it * 256 + tid;
            int r = (idx & 7) + ((idx >> 5) & 15) * 8;
            int c16 = ((idx >> 3) & 3) + (idx >> 9) * 4;
            float4 v = *(const float4*)&rawAf[r * RAWA_ROWW + c16 * 4];
            uint32_t h0, l0, h1, l1;
            split2(v.x, v.y, h0, l0);
            split2(v.z, v.w, h1, l1);
            int w = r * ROWW + c16 * 2;
            *(uint2*)&Ah[w] = make_uint2(h0, h1);
            *(uint2*)&Al[w] = make_uint2(l0, l1);
        }
        // ---- convert B ----
        if (!APPLY) {
            // transpose raw [64d][128n] -> bf16 [n][k]
            int n = tid & 127, dhalf = tid >> 7;
#pragma unroll
            for (int g = 0; g < 4; g++) {
                int db = dhalf * 32 + g * 8;
                float v[8];
#pragma unroll
                for (int dd = 0; dd < 8; dd++) v[dd] = rawBf[(db + dd) * RAWB1_ROWW + n];
                uint32_t H[4], L[4];
#pragma unroll
                for (int j = 0; j < 4; j++) split2(v[2 * j], v[2 * j + 1], H[j], L[j]);
                int w = n * ROWW + dhalf * 16 + g * 4;
                *(uint4*)&Bh[w] = make_uint4(H[0], H[1], H[2], H[3]);
                *(uint4*)&Bl[w] = make_uint4(L[0], L[1], L[2], L[3]);
            }
        } else {
#pragma unroll
            for (int it = 0; it < 8; it++) {
                int idx = it * 256 + tid;
                int r = (idx & 7) + ((idx >> 5) & 15) * 8;
                int c16 = ((idx >> 3) & 3) + (idx >> 9) * 4;
                float4 v = *(const float4*)&rawBf[r * RAWB2_ROWW + c16 * 4];
                int d = d0 + c16 * 4;
                v.x = fmaxf(fmaf(scs[d + 0], v.x, scc[d + 0]), 0.f);
                v.y = fmaxf(fmaf(scs[d + 1], v.y, scc[d + 1]), 0.f);
                v.z = fmaxf(fmaf(scs[d + 2], v.z, scc[d + 2]), 0.f);
                v.w = fmaxf(fmaf(scs[d + 3], v.w, scc[d + 3]), 0.f);
                uint32_t h0, l0, h1, l1;
                split2(v.x, v.y, h0, l0);
                split2(v.z, v.w, h1, l1);
                int w = r * ROWW + c16 * 2;
                *(uint2*)&Bh[w] = make_uint2(h0, h1);
                *(uint2*)&Bl[w] = make_uint2(l0, l1);
            }
        }
        __syncthreads();

        // ---- compute ----
#pragma unroll
        for (int kt = 0; kt < 4; kt++) {
            uint32_t Afh[4][4], Afl[4][4];
#pragma unroll
            for (int mt = 0; mt < 4; mt++) {
                int base = (warp_m * 64 + mt * 16 + rA) * ROWW + kt * 8 + cA;
                Afh[mt][0] = Ah[base];
                Afh[mt][1] = Ah[base + 8 * ROWW];
                Afh[mt][2] = Ah[base + 4];
                Afh[mt][3] = Ah[base + 8 * ROWW + 4];
                Afl[mt][0] = Al[base];
                Afl[mt][1] = Al[base + 8 * ROWW];
                Afl[mt][2] = Al[base + 4];
                Afl[mt][3] = Al[base + 8 * ROWW + 4];
            }
#pragma unroll
            for (int nt = 0; nt < 4; nt++) {
                int bbase = (warp_n * 32 + nt * 8 + rA) * ROWW + kt * 8 + cA;
                uint32_t bh0 = Bh[bbase], bh1 = Bh[bbase + 4];
                uint32_t bl0 = Bl[bbase], bl1 = Bl[bbase + 4];
#pragma unroll
                for (int mt = 0; mt < 4; mt++) {
                    mma16816(acc[mt][nt], Afh[mt], bh0, bh1);
                    mma16816(acc[mt][nt], Afh[mt], bl0, bl1);
                    mma16816(acc[mt][nt], Afl[mt], bh0, bh1);
                }
            }
        }
    }

    // ---- epilogue ----
    __syncthreads();
    float* outb = (APPLY ? g_proj : g_x) + (size_t)bb * HW * 256;
#pragma unroll
    for (int mt = 0; mt < 4; mt++) {
#pragma unroll
        for (int h = 0; h < 2; h++) {
            int e_local = warp_m * 64 + mt * 16 + rA + h * 8;
            int e = mb * 128 + e_local;
            float bv = bsm[e_local];
            float s0 = 0.f, s1 = 0.f;
#pragma unroll
            for (int nt = 0; nt < 4; nt++) {
                int nc = warp_n * 32 + nt * 8 + cA * 2;
                float v0 = acc[mt][nt][h * 2 + 0] + bv;
                float v1 = acc[mt][nt][h * 2 + 1] + bv;
                outb[(size_t)(nb + nc) * 256 + e] = v0;
                outb[(size_t)(nb + nc + 1) * 256 + e] = v1;
                if (!APPLY) {
                    s0 += v0 + v1;
                    s1 += v0 * v0 + v1 * v1;
                } else {
                    s0 += m1f[nc] * v0 + m1f[nc + 1] * v1;
                    s1 += m0f[nc] * v0 + m0f[nc + 1] * v1;
                }
            }
            s0 += __shfl_down_sync(0xffffffffu, s0, 1, 4);
            s0 += __shfl_down_sync(0xffffffffu, s0, 2, 4);
            s1 += __shfl_down_sync(0xffffffffu, s1, 1, 4);
            s1 += __shfl_down_sync(0xffffffffu, s1, 2, 4);
            if (cA == 0) {
                red[(0 * 128 + e_local) * 4 + warp_n] = s0;
                red[(1 * 128 + e_local) * 4 + warp_n] = s1;
            }
        }
    }
    __syncthreads();
    {
        int q = tid >> 7, e_local = tid & 127;
        int e = mb * 128 + e_local;
        const float* r4 = &red[(q * 128 + e_local) * 4];
        float s = r4[0] + r4[1] + r4[2] + r4[3];
        if (!APPLY) {
            if (q == 0)
                g_ps[(size_t)e * 512 + bb * 128 + bx] = s;
            else
                g_pq[(size_t)e * 512 + bb * 128 + bx] = s;
        } else {
            if (q == 0)
                g_pfg[(size_t)(bb * Dm + e) * NBLK + bx] = s;
            else
                g_pbg[(size_t)(bb * Dm + e) * NBLK + bx] = s;
        }
    }
}

// ---------------- finalize BN stats ------------------------------------------
__global__ __launch_bounds__(128) void k_finstats(const float* __restrict__ gamma,
                                                  const float* __restrict__ beta) {
    __shared__ float shs[4], shq[4];
    int e = blockIdx.x, t = threadIdx.x, lane = t & 31, wp = t >> 5;
    float s = 0.f, q = 0.f;
    for (int i = t; i < 512; i += 128) {
        s += g_ps[e * 512 + i];
        q += g_pq[e * 512 + i];
    }
#pragma unroll
    for (int off = 16; off; off >>= 1) {
        s += __shfl_down_sync(0xffffffffu, s, off);
        q += __shfl_down_sync(0xffffffffu, q, off);
    }
    if (lane == 0) {
        shs[wp] = s;
        shq[wp] = q;
    }
    __syncthreads();
    if (t == 0) {
        float ts = shs[0] + shs[1] + shs[2] + shs[3];
        float tq = shq[0] + shq[1] + shq[2] + shq[3];
        const float inv_n = 1.f / (float)(Bm * HW);
        float mean = ts * inv_n;
        float var = fmaxf(tq * inv_n - mean * mean, 0.f);
        float sc = gamma[e] / sqrtf(var + 1e-5f);
        g_s[e] = sc;
        g_c[e] = beta[e] - mean * sc;
    }
}

// ---------------- finalize prototypes ----------------------------------------
__global__ __launch_bounds__(128) void k_finproto() {
    __shared__ float shf[4], shb[4];
    int e = blockIdx.x, b = blockIdx.y, t = threadIdx.x, lane = t & 31, wp = t >> 5;
    float f = g_pfg[(b * Dm + e) * NBLK + t];
    float g = g_pbg[(b * Dm + e) * NBLK + t];
#pragma unroll
    for (int off = 16; off; off >>= 1) {
        f += __shfl_down_sync(0xffffffffu, f, off);
        g += __shfl_down_sync(0xffffffffu, g, off);
    }
    if (lane == 0) {
        shf[wp] = f;
        shb[wp] = g;
    }
    __syncthreads();
    if (t == 0) {
        g_mfg[b * Dm + e] = shf[0] + shf[1] + shf[2] + shf[3];
        g_mbg[b * Dm + e] = shb[0] + shb[1] + shb[2] + shb[3];
    }
}

// ---------------- pair loss ---------------------------------------------------
struct PairSmem {
    unsigned short listA[HW];
    unsigned short listN[HW];
    unsigned long long sbuf[4096];
    float qs[32 * 257];
    float vbuf[8][264];
    int hist[256];
    float red[34];
    int redi[34];
    float warpP[8][33];
    float warpN[8][33];
    int aidx[32];
    float aflag[32];
    int cidx[128];
    float cflag[128];
    int pidx[64];
    float pflag[64];
    int nidx[64];
    float nflag[64];
    int cntA, cntN, coll, bstar;
    float bestv;
    int besti;
};

__device__ __forceinline__ void pair_argmax(PairSmem* S, float v, int i, int tid) {
    int lane = tid & 31, w = tid >> 5;
#pragma unroll
    for (int off = 16; off; off >>= 1) {
        float ov = __shfl_down_sync(0xffffffffu, v, off);
        int oi = __shfl_down_sync(0xffffffffu, i, off);
        if (ov > v || (ov == v && oi < i)) { v = ov; i = oi; }
    }
    if (lane == 0) { S->red[w] = v; S->redi[w] = i; }
    __syncthreads();
    if (w == 0) {
        v = (lane < 8) ? S->red[lane] : -FLT_MAX;
        i = (lane < 8) ? S->redi[lane] : 0x7FFFFFFF;
#pragma unroll
        for (int off = 4; off; off >>= 1) {
            float ov = __shfl_down_sync(0xffffffffu, v, off);
            int oi = __shfl_down_sync(0xffffffffu, i, off);
            if (ov > v || (ov == v && oi < i)) { v = ov; i = oi; }
        }
        if (lane == 0) { S->bestv = v; S->besti = i; }
    }
    __syncthreads();
}

__device__ void select_topk(PairSmem* S, const unsigned short* list, int cnt,
                            const float* __restrict__ key, int K, int* oidx, float* oflag,
                            int tid) {
    float lastv = FLT_MAX;
    int lasti = -1;
    for (int kk = 0; kk < K; kk++) {
        float bv = -FLT_MAX;
        int bi = 0x7FFFFFFF;
        for (int ii = tid; ii < cnt; ii += 256) {
            int idx = list[ii];
            float v = key[idx];
            if (v < lastv || (v == lastv && idx > lasti)) {
                if (v > bv || (v == bv && idx < bi)) { bv = v; bi = idx; }
            }
        }
        pair_argmax(S, bv, bi, tid);
        float gbv = S->bestv;
        int gbi = S->besti;
        if (gbv > -FLT_MAX) {
            lastv = gbv;
            lasti = gbi;
            if (tid == 0) { oidx[kk] = gbi; oflag[kk] = 1.f; }
        } else {
            lastv = -FLT_MAX;
            lasti = 0x7FFFFFFF;
            if (tid == 0) { oidx[kk] = 0; oflag[kk] = 0.f; }
        }
        __syncthreads();
    }
}

__device__ void bitonic_desc(PairSmem* S, int n, int tid) {
    for (int k = 2; k <= n; k <<= 1)
        for (int j = k >> 1; j > 0; j >>= 1) {
            for (int t = tid; t < n; t += 256) {
                int ixj = t ^ j;
                if (ixj > t) {
                    unsigned long long x = S->sbuf[t], y = S->sbuf[ixj];
                    bool desc = ((t & k) == 0);
                    if (desc ? (x < y) : (x > y)) {
                        S->sbuf[t] = y;
                        S->sbuf[ixj] = x;
                    }
                }
            }
            __syncthreads();
        }
}

__device__ void radix_select(PairSmem* S, const unsigned short* list, int cnt,
                             const float* __restrict__ key, int K, int* oidx, float* oflag,
                             int tid) {
    int target = min(K, cnt);
    if (target == 0) {
        for (int kk = tid; kk < K; kk += 256) { oidx[kk] = 0; oflag[kk] = 0.f; }
        __syncthreads();
        return;
    }
    S->hist[tid] = 0;
    __syncthreads();
    for (int ii = tid; ii < cnt; ii += 256) {
        float r = key[list[ii]];
        int b = (int)(r * 256.f);
        b = b < 0 ? 0 : (b > 255 ? 255 : b);
        atomicAdd(&S->hist[b], 1);
    }
    __syncthreads();
    if (tid == 0) {
        int acc = 0, bs = 0;
        for (int b = 255; b >= 0; b--) {
            acc += S->hist[b];
            if (acc >= target) { bs = b; break; }
        }
        S->bstar = bs;
        S->coll = 0;
    }
    __syncthreads();
    int bstar = S->bstar;
    for (int ii = tid; ii < cnt; ii += 256) {
        int idx = list[ii];
        float r = key[idx];
        int b = (int)(r * 256.f);
        b = b < 0 ? 0 : (b > 255 ? 255 : b);
        if (b >= bstar) {
            int p = atomicAdd(&S->coll, 1);
            if (p < 4096)
                S->sbuf[p] = ((unsigned long long)__float_as_uint(r) << 32) |
                             (unsigned long long)(unsigned int)(~(unsigned int)idx);
        }
    }
    __syncthreads();
    int coll = S->coll;
    if (coll > 4096) {
        select_topk(S, list, cnt, key, K, oidx, oflag, tid);
        return;
    }
    int n = 1;
    while (n < coll) n <<= 1;
    for (int i = coll + tid; i < n; i += 256) S->sbuf[i] = 0ull;
    __syncthreads();
    bitonic_desc(S, n, tid);
    for (int kk = tid; kk < K; kk += 256) {
        if (kk < target) {
            oidx[kk] = (int)(~(unsigned int)(S->sbuf[kk] & 0xFFFFFFFFull));
            oflag[kk] = 1.f;
        } else {
            oidx[kk] = 0;
            oflag[kk] = 0.f;
        }
    }
    __syncthreads();
}

__device__ void hard_select(PairSmem* S, const float* __restrict__ ub, int* oidx, float* oflag,
                            int tid) {
    if (tid < 128) {
        unsigned long long kv;
        if (S->cflag[tid] != 0.f) {
            unsigned int u = __float_as_uint(ub[S->cidx[tid]]) + 1u;
            kv = ((unsigned long long)u << 32) |
                 (unsigned long long)(unsigned int)(~(unsigned int)tid);
        } else {
            kv = (unsigned long long)(unsigned int)(~(unsigned int)tid);
        }
        S->sbuf[tid] = kv;
    }
    __syncthreads();
    bitonic_desc(S, 128, tid);
    if (tid < 64) {
        int t = (int)((~(unsigned int)(S->sbuf[tid] & 0xFFFFFFFFull)) & 127u);
        oidx[tid] = S->cidx[t];
        oflag[tid] = S->cflag[t];
    }
    __syncthreads();
}

__global__ __launch_bounds__(256) void k_pair(const float* __restrict__ unc,
                                              const float* __restrict__ r_anc,
                                              const float* __restrict__ r_pos,
                                              const float* __restrict__ r_neg) {
    extern __shared__ char smraw[];
    PairSmem* S = (PairSmem*)smraw;
    int task = blockIdx.x;
    int b = task >> 1, c = task & 1;
    int tid = threadIdx.x, w = tid >> 5, l = tid & 31;
    const unsigned char* am = (c == 0 ? g_m1 : g_m0) + b * HW;
    const unsigned char* nm = (c == 0 ? g_m0 : g_m1) + b * HW;

    if (tid == 0) { S->cntA = 0; S->cntN = 0; }
    __syncthreads();
    for (int i = tid; i < HW; i += 256) {
        if (am[i]) { int p = atomicAdd(&S->cntA, 1); S->listA[p] = (unsigned short)i; }
        if (nm[i]) { int p = atomicAdd(&S->cntN, 1); S->listN[p] = (unsigned short)i; }
    }
    __syncthreads();
    int cntA = S->cntA, cntN = S->cntN;

    const float* ra = r_anc + ((size_t)b * 2 + c) * HW;
    const float* rp = r_pos + ((size_t)b * 2 + c) * HW;
    const float* rn = r_neg + ((size_t)b * 2 + c) * HW;
    const float* ub = unc + (size_t)b * HW;

    radix_select(S, S->listA, cntA, ra, 32, S->aidx, S->aflag, tid);
    radix_select(S, S->listA, cntA, rp, 128, S->cidx, S->cflag, tid);
    hard_select(S, ub, S->pidx, S->pflag, tid);
    radix_select(S, S->listN, cntN, rn, 128, S->cidx, S->cflag, tid);
    hard_select(S, ub, S->nidx, S->nflag, tid);

    const float* projb = g_proj + (size_t)b * HW * 256;  // [n][e] coalesced rows

    for (int q = 0; q < 4; q++) {
        int a = w * 4 + q;
        const float* src = projb + (size_t)S->aidx[a] * 256;
        float v[8], ss = 0.f;
#pragma unroll
        for (int cc = 0; cc < 8; cc++) {
            v[cc] = src[l + 32 * cc];
            ss = fmaf(v[cc], v[cc], ss);
        }
#pragma unroll
        for (int off = 16; off; off >>= 1) ss += __shfl_xor_sync(0xffffffffu, ss, off);
        float sc = 1.f / fmaxf(sqrtf(ss), 1e-12f);
#pragma unroll
        for (int cc = 0; cc < 8; cc++) S->qs[a * 257 + l + 32 * cc] = v[cc] * sc;
    }
    __syncthreads();

    float accP = 0.f, accN = 0.f;
    for (int s = w; s < 128; s += 8) {
        int si = s & 63;
        bool isP = s < 64;
        float fl = isP ? S->pflag[si] : S->nflag[si];
        if (fl != 0.f) {
            int idx = isP ? S->pidx[si] : S->nidx[si];
            const float* src = projb + (size_t)idx * 256;
            float v[8], ss = 0.f;
#pragma unroll
            for (int cc = 0; cc < 8; cc++) {
                v[cc] = src[l + 32 * cc];
                ss = fmaf(v[cc], v[cc], ss);
            }
#pragma unroll
            for (int off = 16; off; off >>= 1) ss += __shfl_xor_sync(0xffffffffu, ss, off);
            float sc = 1.f / fmaxf(sqrtf(ss), 1e-12f);
#pragma unroll
            for (int cc = 0; cc < 8; cc++) S->vbuf[w][l + 32 * cc] = v[cc] * sc;
            __syncwarp();
            float dot = 0.f;
            const float* qrow = &S->qs[l * 257];
#pragma unroll 8
            for (int d = 0; d < 256; d++) dot = fmaf(qrow[d], S->vbuf[w][d], dot);
            float ev = expf(dot * 10.f);
            if (isP) accP += ev; else accN += ev;
            __syncwarp();
        }
    }
    S->warpP[w][l] = accP;
    S->warpN[w][l] = accN;
    __syncthreads();

    if (w == 0) {
        float p = 0.f, n = 0.f;
#pragma unroll
        for (int ww = 0; ww < 8; ww++) {
            p += S->warpP[ww][l];
            n += S->warpN[ww][l];
        }
        bool inc = (cntA >= 1) && (cntN >= 1);
        if (!inc) p += 1.f;
        float per = -logf(p / (p + n + 1e-8f));
        float af = S->aflag[l];
        float ws = per * af, as = af;
#pragma unroll
        for (int off = 16; off; off >>= 1) {
            ws += __shfl_down_sync(0xffffffffu, ws, off);
            as += __shfl_down_sync(0xffffffffu, as, off);
        }
        if (l == 0) {
            g_bl[task] = inc ? (ws / fmaxf(as, 1.f)) : 0.f;
            g_inc[task] = inc ? 1 : 0;
        }
    }
}

// ---------------- final: local + global loss ---------------------------------
__global__ __launch_bounds__(256) void k_final(float* __restrict__ out, int out_size) {
    __shared__ float scratch[34];
    __shared__ float qf[4][257], qb[4][257];
    __shared__ float cf[4], cb[4];
    __shared__ float pfv[4], pbv[4], nfv[4], nbv[4];
    int tid = threadIdx.x;

    for (int b = 0; b < 4; b++) {
        float c1 = 0.f, c0 = 0.f;
        for (int i = tid; i < HW; i += 256) {
            c1 += (float)g_m1[b * HW + i];
            c0 += (float)g_m0[b * HW + i];
        }
        float s1 = blk_sum(scratch, c1, tid);
        float s0 = blk_sum(scratch, c0, tid);
        if (tid == 0) { cf[b] = s1; cb[b] = s0; }
    }
    __syncthreads();

    for (int b = 0; b < 4; b++) {
        float mf = g_mfg[b * Dm + tid] / fmaxf(cf[b], 1.f);
        float mb_ = g_mbg[b * Dm + tid] / fmaxf(cb[b], 1.f);
        float ssf = blk_sum(scratch, mf * mf, tid);
        qf[b][tid] = mf / fmaxf(sqrtf(ssf), 1e-12f);
        float ssb = blk_sum(scratch, mb_ * mb_, tid);
        qb[b][tid] = mb_ / fmaxf(sqrtf(ssb), 1e-12f);
    }
    __syncthreads();

    for (int b = 0; b < 4; b++) {
        float d1 = blk_sum(scratch, qf[b][tid] * qf[b][tid], tid);
        float d2 = blk_sum(scratch, qb[b][tid] * qb[b][tid], tid);
        if (tid == 0) {
            pfv[b] = expf(d1 * 10.f);
            pbv[b] = expf(d2 * 10.f);
            nfv[b] = 0.f;
            nbv[b] = 0.f;
        }
        __syncthreads();
    }
    for (int b = 0; b < 4; b++) {
        for (int j = 0; j <= b; j++) {
            float dqbqf = blk_sum(scratch, qb[j][tid] * qf[b][tid], tid);
            float dqfqb = blk_sum(scratch, qf[j][tid] * qb[b][tid], tid);
            if (tid == 0) {
                bool vgj = (cf[j] >= 1.f) && (cb[j] >= 1.f);
                if (vgj) {
                    nfv[b] += expf(dqbqf * 10.f);
                    nbv[b] += expf(dqfqb * 10.f);
                }
            }
            __syncthreads();
        }
    }

    if (tid == 0) {
        float lsum = 0.f;
        int icnt = 0;
        for (int t = 0; t < 8; t++) {
            lsum += g_bl[t];
            icnt += g_inc[t];
        }
        float l_local = lsum / (float)max(icnt, 1);
        float gs = 0.f;
        int vcnt = 0;
        for (int b = 0; b < 4; b++) {
            bool vg = (cf[b] >= 1.f) && (cb[b] >= 1.f);
            if (vg) {
                float lg = -logf(pfv[b] / (pfv[b] + nfv[b] + 1e-8f)) -
                           logf(pbv[b] / (pbv[b] + nbv[b] + 1e-8f));
                gs += lg;
                vcnt++;
            }
        }
        float l_global = gs / (float)max(vcnt, 1);
        if (out_size > 0) out[0] = l_local + 0.5f * l_global;
        if (out_size > 1) out[1] = l_local;
        if (out_size > 2) out[2] = l_global;
    }
}

// ---------------- launch ------------------------------------------------------
extern "C" void kernel_launch(void* const* d_in, const int* in_sizes, int n_in, void* d_out,
                              int out_size) {
    const float* feat = (const float*)d_in[0];
    const int* labels = (const int*)d_in[1];
    const float* prob_ori = (const float*)d_in[2];
    const float* prob_aug = (const float*)d_in[3];
    const float* unc = (const float*)d_in[4];
    const float* r_anc = (const float*)d_in[5];
    const float* r_pos = (const float*)d_in[6];
    const float* r_neg = (const float*)d_in[7];
    const float* w1 = (const float*)d_in[8];
    const float* b1 = (const float*)d_in[9];
    const float* gamma = (const float*)d_in[10];
    const float* beta = (const float*)d_in[11];
    const float* w2 = (const float*)d_in[12];
    const float* b2 = (const float*)d_in[13];

    cudaFuncSetAttribute(k_gemm_mma<false>, cudaFuncAttributeMaxDynamicSharedMemorySize,
                         GEMM_SMEM);
    cudaFuncSetAttribute(k_gemm_mma<true>, cudaFuncAttributeMaxDynamicSharedMemorySize,
                         GEMM_SMEM);
    cudaFuncSetAttribute(k_pair, cudaFuncAttributeMaxDynamicSharedMemorySize,
                         (int)sizeof(PairSmem));

    k_masks<<<(Bm * HW + 255) / 256, 256>>>(prob_ori, prob_aug, unc, labels);
    dim3 gg(NBLK, 2, Bm);
    k_gemm_mma<false><<<gg, 256, GEMM_SMEM>>>(feat, w1, b1);
    k_finstats<<<Dm, 128>>>(gamma, beta);
    k_gemm_mma<true><<<gg, 256, GEMM_SMEM>>>(nullptr, w2, b2);
    k_finproto<<<dim3(Dm, Bm), 128>>>();
    k_pair<<<8, 256, sizeof(PairSmem)>>>(unc, r_anc, r_pos, r_neg);
    k_final<<<1, 256>>>((float*)d_out, out_size);
}

// round 7
// speedup vs baseline: 1.1060x; 1.1060x over previous
#include <cuda_runtime.h>
#include <cuda_bf16.h>
#include <float.h>
#include <math.h>
#include <stdint.h>

#define HW 16384
#define Dm 256
#define Bm 4
#define NBLK 128

// ---------------- scratch ----------------------------------------------------
__device__ float g_x[Bm * HW * Dm];     // GEMM1 output, layout [b][n][d]
__device__ float g_proj[Bm * HW * Dm];  // GEMM2 output, layout [b][n][e]
__device__ __nv_bfloat16 g_fh[Bm * HW * Dm];  // feat split hi  [b][n][d]
__device__ __nv_bfloat16 g_fl[Bm * HW * Dm];  // feat split lo
__device__ __nv_bfloat16 g_xh[Bm * HW * Dm];  // bn(relu(x)) split hi [b][n][d]
__device__ __nv_bfloat16 g_xl[Bm * HW * Dm];
__device__ __nv_bfloat16 g_w1h[Dm * Dm], g_w1l[Dm * Dm];
__device__ __nv_bfloat16 g_w2h[Dm * Dm], g_w2l[Dm * Dm];
__device__ float g_s[Dm];
__device__ float g_c[Dm];
__device__ unsigned char g_m1[Bm * HW];
__device__ unsigned char g_m0[Bm * HW];
__device__ float g_ps[Dm * 512];
__device__ float g_pq[Dm * 512];
__device__ float g_pfg[Bm * Dm * NBLK];
__device__ float g_pbg[Bm * Dm * NBLK];
__device__ float g_mfg[Bm * Dm];
__device__ float g_mbg[Bm * Dm];
__device__ float g_bl[8];
__device__ int g_inc[8];

// ---------------- block reduction --------------------------------------------
__device__ __forceinline__ float blk_sum(volatile float* scratch, float v, int tid) {
    int lane = tid & 31, w = tid >> 5;
#pragma unroll
    for (int off = 16; off; off >>= 1) v += __shfl_down_sync(0xffffffffu, v, off);
    if (lane == 0) scratch[w] = v;
    __syncthreads();
    if (w == 0) {
        v = (lane < 8) ? scratch[lane] : 0.f;
#pragma unroll
        for (int off = 4; off; off >>= 1) v += __shfl_down_sync(0xffffffffu, v, off);
        if (lane == 0) scratch[32] = v;
    }
    __syncthreads();
    return scratch[32];
}

// ---------------- masks ------------------------------------------------------
__global__ void k_masks(const float* __restrict__ prob_ori, const float* __restrict__ prob_aug,
                        const float* __restrict__ unc, const int* __restrict__ labels) {
    int idx = blockIdx.x * blockDim.x + threadIdx.x;
    if (idx >= Bm * HW) return;
    int b = idx >> 14;
    int hw = idx & (HW - 1);
    const float* po = prob_ori + (size_t)b * 2 * HW;
    const float* pa = prob_aug + (size_t)b * 2 * HW;
    int io = po[HW + hw] > po[hw];
    int ia = pa[HW + hw] > pa[hw];
    bool rel = (io == ia);
    bool diff = unc[idx] > 0.5f;
    int lab = labels[idx];
    bool valid = rel && diff;
    g_m1[idx] = (unsigned char)(valid && lab == 1);
    g_m0[idx] = (unsigned char)(valid && lab == 0);
}

// ---------------- bf16 hi/lo split -------------------------------------------
__device__ __forceinline__ void split2(float a, float b, uint32_t& h, uint32_t& l) {
    __nv_bfloat16 ah = __float2bfloat16_rn(a), bh = __float2bfloat16_rn(b);
    float ar = a - __bfloat162float(ah), br = b - __bfloat162float(bh);
    __nv_bfloat16 al = __float2bfloat16_rn(ar), bl = __float2bfloat16_rn(br);
    h = (uint32_t)*(unsigned short*)&ah | ((uint32_t)*(unsigned short*)&bh << 16);
    l = (uint32_t)*(unsigned short*)&al | ((uint32_t)*(unsigned short*)&bl << 16);
}

__device__ __forceinline__ void mma16816(float* c, const uint32_t* a, uint32_t b0, uint32_t b1) {
    asm volatile(
        "mma.sync.aligned.m16n8k16.row.col.f32.bf16.bf16.f32 "
        "{%0,%1,%2,%3}, {%4,%5,%6,%7}, {%8,%9}, {%0,%1,%2,%3};"
        : "+f"(c[0]), "+f"(c[1]), "+f"(c[2]), "+f"(c[3])
        : "r"(a[0]), "r"(a[1]), "r"(a[2]), "r"(a[3]), "r"(b0), "r"(b1));
}

#define CP16(dst_u32, src_ptr) \
    asm volatile("cp.async.cg.shared.global [%0], [%1], 16;" ::"r"(dst_u32), "l"(src_ptr))
#define CP_COMMIT() asm volatile("cp.async.commit_group;" ::: "memory")
#define CP_WAIT1() asm volatile("cp.async.wait_group 1;" ::: "memory")
#define CP_WAIT0() asm volatile("cp.async.wait_group 0;" ::: "memory")

// ---------------- split weights ----------------------------------------------
__global__ __launch_bounds__(256) void k_splitw(const float* __restrict__ w1,
                                                const float* __restrict__ w2) {
    int sel = blockIdx.y;
    const float* w = sel ? w2 : w1;
    uint32_t* oh = (uint32_t*)(sel ? g_w2h : g_w1h);
    uint32_t* ol = (uint32_t*)(sel ? g_w2l : g_w1l);
    int p = blockIdx.x * 256 + threadIdx.x;  // pair index
    if (p < Dm * Dm / 2) {
        float a = w[2 * p], b = w[2 * p + 1];
        uint32_t h, l;
        split2(a, b, h, l);
        oh[p] = h;
        ol[p] = l;
    }
}

// ---------------- split+transpose feat: [b][d][n] -> bf16 [b][n][d] ----------
__global__ __launch_bounds__(256) void k_split_feat(const float* __restrict__ feat) {
    __shared__ float tile[64 * 65];
    int b = blockIdx.z, d0 = blockIdx.y * 64, n0 = blockIdx.x * 64;
    const float* src = feat + ((size_t)b * Dm + d0) * HW + n0;
    int tid = threadIdx.x;
#pragma unroll
    for (int it = 0; it < 4; it++) {
        int lin = it * 256 + tid;
        int r = lin >> 4, c4 = lin & 15;
        float4 v = *(const float4*)(src + (size_t)r * HW + c4 * 4);
        tile[r * 65 + c4 * 4 + 0] = v.x;
        tile[r * 65 + c4 * 4 + 1] = v.y;
        tile[r * 65 + c4 * 4 + 2] = v.z;
        tile[r * 65 + c4 * 4 + 3] = v.w;
    }
    __syncthreads();
    uint32_t* oh = (uint32_t*)g_fh;
    uint32_t* ol = (uint32_t*)g_fl;
#pragma unroll
    for (int it = 0; it < 8; it++) {
        int lin = it * 256 + tid;
        int n = lin >> 5, c = lin & 31;  // c = d-pair
        float v0 = tile[(2 * c) * 65 + n];
        float v1 = tile[(2 * c + 1) * 65 + n];
        uint32_t h, l;
        split2(v0, v1, h, l);
        size_t o = (((size_t)b * HW + n0 + n) * 256 + d0) / 2 + c;
        oh[o] = h;
        ol[o] = l;
    }
}

// ---------------- bn+relu+split: g_x -> g_xh/g_xl ----------------------------
__global__ __launch_bounds__(256) void k_bnsplit() {
    __shared__ float scs[256], scc[256];
    int tid = threadIdx.x;
    scs[tid] = g_s[tid];
    scc[tid] = g_c[tid];
    __syncthreads();
    size_t row = (size_t)blockIdx.x * 8 + (tid >> 5);
    int d0 = (tid & 31) * 8;
    const float* src = g_x + row * 256 + d0;
    float4 a = *(const float4*)src, b4 = *(const float4*)(src + 4);
    float v[8] = {a.x, a.y, a.z, a.w, b4.x, b4.y, b4.z, b4.w};
#pragma unroll
    for (int j = 0; j < 8; j++) v[j] = fmaxf(fmaf(scs[d0 + j], v[j], scc[d0 + j]), 0.f);
    uint32_t H[4], L[4];
#pragma unroll
    for (int j = 0; j < 4; j++) split2(v[2 * j], v[2 * j + 1], H[j], L[j]);
    size_t o = row * 128 + d0 / 2;
    *(uint4*)&((uint32_t*)g_xh)[o] = make_uint4(H[0], H[1], H[2], H[3]);
    *(uint4*)&((uint32_t*)g_xl)[o] = make_uint4(L[0], L[1], L[2], L[3]);
}

// ---------------- pure-bf16 HMMA GEMM: C[e,n] = sum_d A[e,d]*B[n,d] + bias ---
// cp.async depth-2 pipeline of pre-split bf16 tiles. No conversion in-kernel.
#define ROWW 36                 // words per padded row (64 halves + 8 pad)
#define MATW (128 * ROWW)       // 4608 words per matrix
#define STAGEW (4 * MATW)       // Ah,Al,Bh,Bl per stage
#define OFF_EXT (2 * STAGEW)    // 36864 words
#define GEMM_SMEM ((OFF_EXT + 1408) * 4)  // 153088 bytes

template <bool APPLY>
__global__ __launch_bounds__(256, 1) void k_gemm_mma(const float* __restrict__ bias) {
    extern __shared__ __align__(16) char smraw[];
    uint32_t* smw = (uint32_t*)smraw;
    float* ext = (float*)smraw + OFF_EXT;
    float* bsm = ext;        // [128]
    float* m1f = ext + 128;  // [128]
    float* m0f = ext + 256;  // [128]
    float* red = ext + 384;  // [2][128][4]
    const uint32_t sb = (uint32_t)__cvta_generic_to_shared(smraw);

    const int tid = threadIdx.x, lane = tid & 31, wid = tid >> 5;
    const int warp_m = wid >> 2, warp_n = wid & 3;
    const int bx = blockIdx.x, mb = blockIdx.y, bb = blockIdx.z;
    const int nb = bx * 128;

    if (tid < 128) bsm[tid] = bias[mb * 128 + tid];
    if (APPLY && tid < 128) {
        m1f[tid] = (float)g_m1[bb * HW + nb + tid];
        m0f[tid] = (float)g_m0[bb * HW + nb + tid];
    }

    const __nv_bfloat16* WH = APPLY ? g_w2h : g_w1h;
    const __nv_bfloat16* WL = APPLY ? g_w2l : g_w1l;
    const __nv_bfloat16* BH = (APPLY ? g_xh : g_fh) + (size_t)bb * HW * 256;
    const __nv_bfloat16* BL = (APPLY ? g_xl : g_fl) + (size_t)bb * HW * 256;

    float acc[4][4][4];
#pragma unroll
    for (int i = 0; i < 4; i++)
#pragma unroll
        for (int j = 0; j < 4; j++)
#pragma unroll
            for (int k = 0; k < 4; k++) acc[i][j][k] = 0.f;

    const int rA = lane >> 2, cA = lane & 3;

    auto issue = [&](int kc, int stage) {
        const int d0 = kc * 64;
        uint32_t base = sb + stage * STAGEW * 4;
#pragma unroll
        for (int it = 0; it < 4; it++) {
            int lin = it * 256 + tid;
            int r = lin >> 3, c = lin & 7;
            uint32_t doff = (r * ROWW + c * 4) * 4;
            size_t aoff = ((size_t)(mb * 128 + r) * 256 + d0 + c * 8);
            size_t boff = ((size_t)(nb + r) * 256 + d0 + c * 8);
            CP16(base + doff, (const char*)WH + aoff * 2);
            CP16(base + MATW * 4 + doff, (const char*)WL + aoff * 2);
            CP16(base + 2 * MATW * 4 + doff, (const char*)BH + boff * 2);
            CP16(base + 3 * MATW * 4 + doff, (const char*)BL + boff * 2);
        }
        CP_COMMIT();
    };

    issue(0, 0);
    issue(1, 1);

#pragma unroll 1
    for (int kc = 0; kc < 4; kc++) {
        const int stage = kc & 1;
        if (kc < 3) CP_WAIT1(); else CP_WAIT0();
        __syncthreads();
        const uint32_t* Ah = smw + stage * STAGEW;
        const uint32_t* Al = Ah + MATW;
        const uint32_t* Bh = Al + MATW;
        const uint32_t* Bl = Bh + MATW;
#pragma unroll
        for (int kt = 0; kt < 4; kt++) {
            uint32_t Afh[4][4], Afl[4][4];
#pragma unroll
            for (int mt = 0; mt < 4; mt++) {
                int base = (warp_m * 64 + mt * 16 + rA) * ROWW + kt * 8 + cA;
                Afh[mt][0] = Ah[base];
                Afh[mt][1] = Ah[base + 8 * ROWW];
                Afh[mt][2] = Ah[base + 4];
                Afh[mt][3] = Ah[base + 8 * ROWW + 4];
                Afl[mt][0] = Al[base];
                Afl[mt][1] = Al[base + 8 * ROWW];
                Afl[mt][2] = Al[base + 4];
                Afl[mt][3] = Al[base + 8 * ROWW + 4];
            }
#pragma unroll
            for (int nt = 0; nt < 4; nt++) {
                int bbase = (warp_n * 32 + nt * 8 + rA) * ROWW + kt * 8 + cA;
                uint32_t bh0 = Bh[bbase], bh1 = Bh[bbase + 4];
                uint32_t bl0 = Bl[bbase], bl1 = Bl[bbase + 4];
#pragma unroll
                for (int mt = 0; mt < 4; mt++) {
                    mma16816(acc[mt][nt], Afh[mt], bh0, bh1);
                    mma16816(acc[mt][nt], Afh[mt], bl0, bl1);
                    mma16816(acc[mt][nt], Afl[mt], bh0, bh1);
                }
            }
        }
        __syncthreads();
        if (kc + 2 <= 3) issue(kc + 2, stage);
    }

    // ---- epilogue ----
    float* outb = (APPLY ? g_proj : g_x) + (size_t)bb * HW * 256;
#pragma unroll
    for (int mt = 0; mt < 4; mt++) {
#pragma unroll
        for (int h = 0; h < 2; h++) {
            int e_local = warp_m * 64 + mt * 16 + rA + h * 8;
            int e = mb * 128 + e_local;
            float bv = bsm[e_local];
            float s0 = 0.f, s1 = 0.f;
#pragma unroll
            for (int nt = 0; nt < 4; nt++) {
                int nc = warp_n * 32 + nt * 8 + cA * 2;
                float v0 = acc[mt][nt][h * 2 + 0] + bv;
                float v1 = acc[mt][nt][h * 2 + 1] + bv;
                outb[(size_t)(nb + nc) * 256 + e] = v0;
                outb[(size_t)(nb + nc + 1) * 256 + e] = v1;
                if (!APPLY) {
                    s0 += v0 + v1;
                    s1 += v0 * v0 + v1 * v1;
                } else {
                    s0 += m1f[nc] * v0 + m1f[nc + 1] * v1;
                    s1 += m0f[nc] * v0 + m0f[nc + 1] * v1;
                }
            }
            s0 += __shfl_down_sync(0xffffffffu, s0, 1, 4);
            s0 += __shfl_down_sync(0xffffffffu, s0, 2, 4);
            s1 += __shfl_down_sync(0xffffffffu, s1, 1, 4);
            s1 += __shfl_down_sync(0xffffffffu, s1, 2, 4);
            if (cA == 0) {
                red[(0 * 128 + e_local) * 4 + warp_n] = s0;
                red[(1 * 128 + e_local) * 4 + warp_n] = s1;
            }
        }
    }
    __syncthreads();
    {
        int q = tid >> 7, e_local = tid & 127;
        int e = mb * 128 + e_local;
        const float* r4 = &red[(q * 128 + e_local) * 4];
        float s = r4[0] + r4[1] + r4[2] + r4[3];
        if (!APPLY) {
            if (q == 0)
                g_ps[(size_t)e * 512 + bb * 128 + bx] = s;
            else
                g_pq[(size_t)e * 512 + bb * 128 + bx] = s;
        } else {
            if (q == 0)
                g_pfg[(size_t)(bb * Dm + e) * NBLK + bx] = s;
            else
                g_pbg[(size_t)(bb * Dm + e) * NBLK + bx] = s;
        }
    }
}

// ---------------- finalize BN stats ------------------------------------------
__global__ __launch_bounds__(128) void k_finstats(const float* __restrict__ gamma,
                                                  const float* __restrict__ beta) {
    __shared__ float shs[4], shq[4];
    int e = blockIdx.x, t = threadIdx.x, lane = t & 31, wp = t >> 5;
    float s = 0.f, q = 0.f;
    for (int i = t; i < 512; i += 128) {
        s += g_ps[e * 512 + i];
        q += g_pq[e * 512 + i];
    }
#pragma unroll
    for (int off = 16; off; off >>= 1) {
        s += __shfl_down_sync(0xffffffffu, s, off);
        q += __shfl_down_sync(0xffffffffu, q, off);
    }
    if (lane == 0) {
        shs[wp] = s;
        shq[wp] = q;
    }
    __syncthreads();
    if (t == 0) {
        float ts = shs[0] + shs[1] + shs[2] + shs[3];
        float tq = shq[0] + shq[1] + shq[2] + shq[3];
        const float inv_n = 1.f / (float)(Bm * HW);
        float mean = ts * inv_n;
        float var = fmaxf(tq * inv_n - mean * mean, 0.f);
        float sc = gamma[e] / sqrtf(var + 1e-5f);
        g_s[e] = sc;
        g_c[e] = beta[e] - mean * sc;
    }
}

// ---------------- finalize prototypes ----------------------------------------
__global__ __launch_bounds__(128) void k_finproto() {
    __shared__ float shf[4], shb[4];
    int e = blockIdx.x, b = blockIdx.y, t = threadIdx.x, lane = t & 31, wp = t >> 5;
    float f = g_pfg[(b * Dm + e) * NBLK + t];
    float g = g_pbg[(b * Dm + e) * NBLK + t];
#pragma unroll
    for (int off = 16; off; off >>= 1) {
        f += __shfl_down_sync(0xffffffffu, f, off);
        g += __shfl_down_sync(0xffffffffu, g, off);
    }
    if (lane == 0) {
        shf[wp] = f;
        shb[wp] = g;
    }
    __syncthreads();
    if (t == 0) {
        g_mfg[b * Dm + e] = shf[0] + shf[1] + shf[2] + shf[3];
        g_mbg[b * Dm + e] = shb[0] + shb[1] + shb[2] + shb[3];
    }
}

// ---------------- pair loss ---------------------------------------------------
struct PairSmem {
    unsigned short listA[HW];
    unsigned short listN[HW];
    unsigned long long sbuf[4096];
    float qs[32 * 257];
    float vbuf[8][264];
    int hist[256];
    float red[34];
    int redi[34];
    float warpP[8][33];
    float warpN[8][33];
    int aidx[32];
    float aflag[32];
    int cidx[128];
    float cflag[128];
    int pidx[64];
    float pflag[64];
    int nidx[64];
    float nflag[64];
    int cntA, cntN, coll, bstar;
    float bestv;
    int besti;
};

__device__ __forceinline__ void pair_argmax(PairSmem* S, float v, int i, int tid) {
    int lane = tid & 31, w = tid >> 5;
#pragma unroll
    for (int off = 16; off; off >>= 1) {
        float ov = __shfl_down_sync(0xffffffffu, v, off);
        int oi = __shfl_down_sync(0xffffffffu, i, off);
        if (ov > v || (ov == v && oi < i)) { v = ov; i = oi; }
    }
    if (lane == 0) { S->red[w] = v; S->redi[w] = i; }
    __syncthreads();
    if (w == 0) {
        v = (lane < 8) ? S->red[lane] : -FLT_MAX;
        i = (lane < 8) ? S->redi[lane] : 0x7FFFFFFF;
#pragma unroll
        for (int off = 4; off; off >>= 1) {
            float ov = __shfl_down_sync(0xffffffffu, v, off);
            int oi = __shfl_down_sync(0xffffffffu, i, off);
            if (ov > v || (ov == v && oi < i)) { v = ov; i = oi; }
        }
        if (lane == 0) { S->bestv = v; S->besti = i; }
    }
    __syncthreads();
}

__device__ void select_topk(PairSmem* S, const unsigned short* list, int cnt,
                            const float* __restrict__ key, int K, int* oidx, float* oflag,
                            int tid) {
    float lastv = FLT_MAX;
    int lasti = -1;
    for (int kk = 0; kk < K; kk++) {
        float bv = -FLT_MAX;
        int bi = 0x7FFFFFFF;
        for (int ii = tid; ii < cnt; ii += 256) {
            int idx = list[ii];
            float v = key[idx];
            if (v < lastv || (v == lastv && idx > lasti)) {
                if (v > bv || (v == bv && idx < bi)) { bv = v; bi = idx; }
            }
        }
        pair_argmax(S, bv, bi, tid);
        float gbv = S->bestv;
        int gbi = S->besti;
        if (gbv > -FLT_MAX) {
            lastv = gbv;
            lasti = gbi;
            if (tid == 0) { oidx[kk] = gbi; oflag[kk] = 1.f; }
        } else {
            lastv = -FLT_MAX;
            lasti = 0x7FFFFFFF;
            if (tid == 0) { oidx[kk] = 0; oflag[kk] = 0.f; }
        }
        __syncthreads();
    }
}

__device__ void bitonic_desc(PairSmem* S, int n, int tid) {
    for (int k = 2; k <= n; k <<= 1)
        for (int j = k >> 1; j > 0; j >>= 1) {
            for (int t = tid; t < n; t += 256) {
                int ixj = t ^ j;
                if (ixj > t) {
                    unsigned long long x = S->sbuf[t], y = S->sbuf[ixj];
                    bool desc = ((t & k) == 0);
                    if (desc ? (x < y) : (x > y)) {
                        S->sbuf[t] = y;
                        S->sbuf[ixj] = x;
                    }
                }
            }
            __syncthreads();
        }
}

__device__ void radix_select(PairSmem* S, const unsigned short* list, int cnt,
                             const float* __restrict__ key, int K, int* oidx, float* oflag,
                             int tid) {
    int target = min(K, cnt);
    if (target == 0) {
        for (int kk = tid; kk < K; kk += 256) { oidx[kk] = 0; oflag[kk] = 0.f; }
        __syncthreads();
        return;
    }
    S->hist[tid] = 0;
    __syncthreads();
    for (int ii = tid; ii < cnt; ii += 256) {
        float r = key[list[ii]];
        int b = (int)(r * 256.f);
        b = b < 0 ? 0 : (b > 255 ? 255 : b);
        atomicAdd(&S->hist[b], 1);
    }
    __syncthreads();
    if (tid == 0) {
        int acc = 0, bs = 0;
        for (int b = 255; b >= 0; b--) {
            acc += S->hist[b];
            if (acc >= target) { bs = b; break; }
        }
        S->bstar = bs;
        S->coll = 0;
    }
    __syncthreads();
    int bstar = S->bstar;
    for (int ii = tid; ii < cnt; ii += 256) {
        int idx = list[ii];
        float r = key[idx];
        int b = (int)(r * 256.f);
        b = b < 0 ? 0 : (b > 255 ? 255 : b);
        if (b >= bstar) {
            int p = atomicAdd(&S->coll, 1);
            if (p < 4096)
                S->sbuf[p] = ((unsigned long long)__float_as_uint(r) << 32) |
                             (unsigned long long)(unsigned int)(~(unsigned int)idx);
        }
    }
    __syncthreads();
    int coll = S->coll;
    if (coll > 4096) {
        select_topk(S, list, cnt, key, K, oidx, oflag, tid);
        return;
    }
    int n = 1;
    while (n < coll) n <<= 1;
    for (int i = coll + tid; i < n; i += 256) S->sbuf[i] = 0ull;
    __syncthreads();
    bitonic_desc(S, n, tid);
    for (int kk = tid; kk < K; kk += 256) {
        if (kk < target) {
            oidx[kk] = (int)(~(unsigned int)(S->sbuf[kk] & 0xFFFFFFFFull));
            oflag[kk] = 1.f;
        } else {
            oidx[kk] = 0;
            oflag[kk] = 0.f;
        }
    }
    __syncthreads();
}

__device__ void hard_select(PairSmem* S, const float* __restrict__ ub, int* oidx, float* oflag,
                            int tid) {
    if (tid < 128) {
        unsigned long long kv;
        if (S->cflag[tid] != 0.f) {
            unsigned int u = __float_as_uint(ub[S->cidx[tid]]) + 1u;
            kv = ((unsigned long long)u << 32) |
                 (unsigned long long)(unsigned int)(~(unsigned int)tid);
        } else {
            kv = (unsigned long long)(unsigned int)(~(unsigned int)tid);
        }
        S->sbuf[tid] = kv;
    }
    __syncthreads();
    bitonic_desc(S, 128, tid);
    if (tid < 64) {
        int t = (int)((~(unsigned int)(S->sbuf[tid] & 0xFFFFFFFFull)) & 127u);
        oidx[tid] = S->cidx[t];
        oflag[tid] = S->cflag[t];
    }
    __syncthreads();
}

__global__ __launch_bounds__(256) void k_pair(const float* __restrict__ unc,
                                              const float* __restrict__ r_anc,
                                              const float* __restrict__ r_pos,
                                              const float* __restrict__ r_neg) {
    extern __shared__ char smraw[];
    PairSmem* S = (PairSmem*)smraw;
    int task = blockIdx.x;
    int b = task >> 1, c = task & 1;
    int tid = threadIdx.x, w = tid >> 5, l = tid & 31;
    const unsigned char* am = (c == 0 ? g_m1 : g_m0) + b * HW;
    const unsigned char* nm = (c == 0 ? g_m0 : g_m1) + b * HW;

    if (tid == 0) { S->cntA = 0; S->cntN = 0; }
    __syncthreads();
    for (int i = tid; i < HW; i += 256) {
        if (am[i]) { int p = atomicAdd(&S->cntA, 1); S->listA[p] = (unsigned short)i; }
        if (nm[i]) { int p = atomicAdd(&S->cntN, 1); S->listN[p] = (unsigned short)i; }
    }
    __syncthreads();
    int cntA = S->cntA, cntN = S->cntN;

    const float* ra = r_anc + ((size_t)b * 2 + c) * HW;
    const float* rp = r_pos + ((size_t)b * 2 + c) * HW;
    const float* rn = r_neg + ((size_t)b * 2 + c) * HW;
    const float* ub = unc + (size_t)b * HW;

    radix_select(S, S->listA, cntA, ra, 32, S->aidx, S->aflag, tid);
    radix_select(S, S->listA, cntA, rp, 128, S->cidx, S->cflag, tid);
    hard_select(S, ub, S->pidx, S->pflag, tid);
    radix_select(S, S->listN, cntN, rn, 128, S->cidx, S->cflag, tid);
    hard_select(S, ub, S->nidx, S->nflag, tid);

    const float* projb = g_proj + (size_t)b * HW * 256;

    for (int q = 0; q < 4; q++) {
        int a = w * 4 + q;
        const float* src = projb + (size_t)S->aidx[a] * 256;
        float v[8], ss = 0.f;
#pragma unroll
        for (int cc = 0; cc < 8; cc++) {
            v[cc] = src[l + 32 * cc];
            ss = fmaf(v[cc], v[cc], ss);
        }
#pragma unroll
        for (int off = 16; off; off >>= 1) ss += __shfl_xor_sync(0xffffffffu, ss, off);
        float sc = 1.f / fmaxf(sqrtf(ss), 1e-12f);
#pragma unroll
        for (int cc = 0; cc < 8; cc++) S->qs[a * 257 + l + 32 * cc] = v[cc] * sc;
    }
    __syncthreads();

    float accP = 0.f, accN = 0.f;
    for (int s = w; s < 128; s += 8) {
        int si = s & 63;
        bool isP = s < 64;
        float fl = isP ? S->pflag[si] : S->nflag[si];
        if (fl != 0.f) {
            int idx = isP ? S->pidx[si] : S->nidx[si];
            const float* src = projb + (size_t)idx * 256;
            float v[8], ss = 0.f;
#pragma unroll
            for (int cc = 0; cc < 8; cc++) {
                v[cc] = src[l + 32 * cc];
                ss = fmaf(v[cc], v[cc], ss);
            }
#pragma unroll
            for (int off = 16; off; off >>= 1) ss += __shfl_xor_sync(0xffffffffu, ss, off);
            float sc = 1.f / fmaxf(sqrtf(ss), 1e-12f);
#pragma unroll
            for (int cc = 0; cc < 8; cc++) S->vbuf[w][l + 32 * cc] = v[cc] * sc;
            __syncwarp();
            float dot = 0.f;
            const float* qrow = &S->qs[l * 257];
#pragma unroll 8
            for (int d = 0; d < 256; d++) dot = fmaf(qrow[d], S->vbuf[w][d], dot);
            float ev = expf(dot * 10.f);
            if (isP) accP += ev; else accN += ev;
            __syncwarp();
        }
    }
    S->warpP[w][l] = accP;
    S->warpN[w][l] = accN;
    __syncthreads();

    if (w == 0) {
        float p = 0.f, n = 0.f;
#pragma unroll
        for (int ww = 0; ww < 8; ww++) {
            p += S->warpP[ww][l];
            n += S->warpN[ww][l];
        }
        bool inc = (cntA >= 1) && (cntN >= 1);
        if (!inc) p += 1.f;
        float per = -logf(p / (p + n + 1e-8f));
        float af = S->aflag[l];
        float ws = per * af, as = af;
#pragma unroll
        for (int off = 16; off; off >>= 1) {
            ws += __shfl_down_sync(0xffffffffu, ws, off);
            as += __shfl_down_sync(0xffffffffu, as, off);
        }
        if (l == 0) {
            g_bl[task] = inc ? (ws / fmaxf(as, 1.f)) : 0.f;
            g_inc[task] = inc ? 1 : 0;
        }
    }
}

// ---------------- final: local + global loss ---------------------------------
__global__ __launch_bounds__(256) void k_final(float* __restrict__ out, int out_size) {
    __shared__ float scratch[34];
    __shared__ float qf[4][257], qb[4][257];
    __shared__ float cf[4], cb[4];
    __shared__ float pfv[4], pbv[4], nfv[4], nbv[4];
    int tid = threadIdx.x;

    for (int b = 0; b < 4; b++) {
        float c1 = 0.f, c0 = 0.f;
        for (int i = tid; i < HW; i += 256) {
            c1 += (float)g_m1[b * HW + i];
            c0 += (float)g_m0[b * HW + i];
        }
        float s1 = blk_sum(scratch, c1, tid);
        float s0 = blk_sum(scratch, c0, tid);
        if (tid == 0) { cf[b] = s1; cb[b] = s0; }
    }
    __syncthreads();

    for (int b = 0; b < 4; b++) {
        float mf = g_mfg[b * Dm + tid] / fmaxf(cf[b], 1.f);
        float mb_ = g_mbg[b * Dm + tid] / fmaxf(cb[b], 1.f);
        float ssf = blk_sum(scratch, mf * mf, tid);
        qf[b][tid] = mf / fmaxf(sqrtf(ssf), 1e-12f);
        float ssb = blk_sum(scratch, mb_ * mb_, tid);
        qb[b][tid] = mb_ / fmaxf(sqrtf(ssb), 1e-12f);
    }
    __syncthreads();

    for (int b = 0; b < 4; b++) {
        float d1 = blk_sum(scratch, qf[b][tid] * qf[b][tid], tid);
        float d2 = blk_sum(scratch, qb[b][tid] * qb[b][tid], tid);
        if (tid == 0) {
            pfv[b] = expf(d1 * 10.f);
            pbv[b] = expf(d2 * 10.f);
            nfv[b] = 0.f;
            nbv[b] = 0.f;
        }
        __syncthreads();
    }
    for (int b = 0; b < 4; b++) {
        for (int j = 0; j <= b; j++) {
            float dqbqf = blk_sum(scratch, qb[j][tid] * qf[b][tid], tid);
            float dqfqb = blk_sum(scratch, qf[j][tid] * qb[b][tid], tid);
            if (tid == 0) {
                bool vgj = (cf[j] >= 1.f) && (cb[j] >= 1.f);
                if (vgj) {
                    nfv[b] += expf(dqbqf * 10.f);
                    nbv[b] += expf(dqfqb * 10.f);
                }
            }
            __syncthreads();
        }
    }

    if (tid == 0) {
        float lsum = 0.f;
        int icnt = 0;
        for (int t = 0; t < 8; t++) {
            lsum += g_bl[t];
            icnt += g_inc[t];
        }
        float l_local = lsum / (float)max(icnt, 1);
        float gs = 0.f;
        int vcnt = 0;
        for (int b = 0; b < 4; b++) {
            bool vg = (cf[b] >= 1.f) && (cb[b] >= 1.f);
            if (vg) {
                float lg = -logf(pfv[b] / (pfv[b] + nfv[b] + 1e-8f)) -
                           logf(pbv[b] / (pbv[b] + nbv[b] + 1e-8f));
                gs += lg;
                vcnt++;
            }
        }
        float l_global = gs / (float)max(vcnt, 1);
        if (out_size > 0) out[0] = l_local + 0.5f * l_global;
        if (out_size > 1) out[1] = l_local;
        if (out_size > 2) out[2] = l_global;
    }
}

// ---------------- launch ------------------------------------------------------
extern "C" void kernel_launch(void* const* d_in, const int* in_sizes, int n_in, void* d_out,
                              int out_size) {
    const float* feat = (const float*)d_in[0];
    const int* labels = (const int*)d_in[1];
    const float* prob_ori = (const float*)d_in[2];
    const float* prob_aug = (const float*)d_in[3];
    const float* unc = (const float*)d_in[4];
    const float* r_anc = (const float*)d_in[5];
    const float* r_pos = (const float*)d_in[6];
    const float* r_neg = (const float*)d_in[7];
    const float* w1 = (const float*)d_in[8];
    const float* b1 = (const float*)d_in[9];
    const float* gamma = (const float*)d_in[10];
    const float* beta = (const float*)d_in[11];
    const float* w2 = (const float*)d_in[12];
    const float* b2 = (const float*)d_in[13];

    cudaFuncSetAttribute(k_gemm_mma<false>, cudaFuncAttributeMaxDynamicSharedMemorySize,
                         GEMM_SMEM);
    cudaFuncSetAttribute(k_gemm_mma<true>, cudaFuncAttributeMaxDynamicSharedMemorySize,
                         GEMM_SMEM);
    cudaFuncSetAttribute(k_pair, cudaFuncAttributeMaxDynamicSharedMemorySize,
                         (int)sizeof(PairSmem));

    k_masks<<<(Bm * HW + 255) / 256, 256>>>(prob_ori, prob_aug, unc, labels);
    k_splitw<<<dim3(Dm * Dm / 2 / 256, 2), 256>>>(w1, w2);
    k_split_feat<<<dim3(HW / 64, Dm / 64, Bm), 256>>>(feat);
    dim3 gg(NBLK, 2, Bm);
    k_gemm_mma<false><<<gg, 256, GEMM_SMEM>>>(b1);
    k_finstats<<<Dm, 128>>>(gamma, beta);
    k_bnsplit<<<Bm * HW / 8, 256>>>();
    k_gemm_mma<true><<<gg, 256, GEMM_SMEM>>>(b2);
    k_finproto<<<dim3(Dm, Bm), 128>>>();
    k_pair<<<8, 256, sizeof(PairSmem)>>>(unc, r_anc, r_pos, r_neg);
    k_final<<<1, 256>>>((float*)d_out, out_size);
}

// round 8
// speedup vs baseline: 1.1571x; 1.0462x over previous
#include <cuda_runtime.h>
#include <cuda_bf16.h>
#include <float.h>
#include <math.h>
#include <stdint.h>

#define HW 16384
#define Dm 256
#define Bm 4
#define NBLK 128

// ---------------- scratch ----------------------------------------------------
__device__ float g_x[Bm * HW * Dm];     // GEMM1 output, layout [b][n][d]
__device__ float g_proj[Bm * HW * Dm];  // GEMM2 output, layout [b][n][e]
__device__ __nv_bfloat16 g_fh[Bm * HW * Dm];  // feat split hi  [b][n][d]
__device__ __nv_bfloat16 g_fl[Bm * HW * Dm];  // feat split lo
__device__ __nv_bfloat16 g_xh[Bm * HW * Dm];  // bn(relu(x)) split hi [b][n][d]
__device__ __nv_bfloat16 g_xl[Bm * HW * Dm];
__device__ __nv_bfloat16 g_w1h[Dm * Dm], g_w1l[Dm * Dm];
__device__ __nv_bfloat16 g_w2h[Dm * Dm], g_w2l[Dm * Dm];
__device__ float g_s[Dm];
__device__ float g_c[Dm];
__device__ unsigned char g_m1[Bm * HW];
__device__ unsigned char g_m0[Bm * HW];
__device__ float g_ps[Dm * 512];
__device__ float g_pq[Dm * 512];
__device__ float g_pfg[Bm * Dm * NBLK];
__device__ float g_pbg[Bm * Dm * NBLK];
__device__ float g_mfg[Bm * Dm];
__device__ float g_mbg[Bm * Dm];
__device__ float g_bl[8];
__device__ int g_inc[8];

// ---------------- block reduction --------------------------------------------
__device__ __forceinline__ float blk_sum(volatile float* scratch, float v, int tid) {
    int lane = tid & 31, w = tid >> 5;
#pragma unroll
    for (int off = 16; off; off >>= 1) v += __shfl_down_sync(0xffffffffu, v, off);
    if (lane == 0) scratch[w] = v;
    __syncthreads();
    if (w == 0) {
        v = (lane < 8) ? scratch[lane] : 0.f;
#pragma unroll
        for (int off = 4; off; off >>= 1) v += __shfl_down_sync(0xffffffffu, v, off);
        if (lane == 0) scratch[32] = v;
    }
    __syncthreads();
    return scratch[32];
}

// ---------------- masks ------------------------------------------------------
__global__ void k_masks(const float* __restrict__ prob_ori, const float* __restrict__ prob_aug,
                        const float* __restrict__ unc, const int* __restrict__ labels) {
    int idx = blockIdx.x * blockDim.x + threadIdx.x;
    if (idx >= Bm * HW) return;
    int b = idx >> 14;
    int hw = idx & (HW - 1);
    const float* po = prob_ori + (size_t)b * 2 * HW;
    const float* pa = prob_aug + (size_t)b * 2 * HW;
    int io = po[HW + hw] > po[hw];
    int ia = pa[HW + hw] > pa[hw];
    bool rel = (io == ia);
    bool diff = unc[idx] > 0.5f;
    int lab = labels[idx];
    bool valid = rel && diff;
    g_m1[idx] = (unsigned char)(valid && lab == 1);
    g_m0[idx] = (unsigned char)(valid && lab == 0);
}

// ---------------- bf16 hi/lo split -------------------------------------------
__device__ __forceinline__ void split2(float a, float b, uint32_t& h, uint32_t& l) {
    __nv_bfloat16 ah = __float2bfloat16_rn(a), bh = __float2bfloat16_rn(b);
    float ar = a - __bfloat162float(ah), br = b - __bfloat162float(bh);
    __nv_bfloat16 al = __float2bfloat16_rn(ar), bl = __float2bfloat16_rn(br);
    h = (uint32_t)*(unsigned short*)&ah | ((uint32_t)*(unsigned short*)&bh << 16);
    l = (uint32_t)*(unsigned short*)&al | ((uint32_t)*(unsigned short*)&bl << 16);
}

__device__ __forceinline__ void mma16816(float* c, const uint32_t* a, uint32_t b0, uint32_t b1) {
    asm volatile(
        "mma.sync.aligned.m16n8k16.row.col.f32.bf16.bf16.f32 "
        "{%0,%1,%2,%3}, {%4,%5,%6,%7}, {%8,%9}, {%0,%1,%2,%3};"
        : "+f"(c[0]), "+f"(c[1]), "+f"(c[2]), "+f"(c[3])
        : "r"(a[0]), "r"(a[1]), "r"(a[2]), "r"(a[3]), "r"(b0), "r"(b1));
}

#define CP16(dst_u32, src_ptr) \
    asm volatile("cp.async.cg.shared.global [%0], [%1], 16;" ::"r"(dst_u32), "l"(src_ptr))
#define CP_COMMIT() asm volatile("cp.async.commit_group;" ::: "memory")
#define CP_WAIT1() asm volatile("cp.async.wait_group 1;" ::: "memory")
#define CP_WAIT0() asm volatile("cp.async.wait_group 0;" ::: "memory")

// ---------------- split weights ----------------------------------------------
__global__ __launch_bounds__(256) void k_splitw(const float* __restrict__ w1,
                                                const float* __restrict__ w2) {
    int sel = blockIdx.y;
    const float* w = sel ? w2 : w1;
    uint32_t* oh = (uint32_t*)(sel ? g_w2h : g_w1h);
    uint32_t* ol = (uint32_t*)(sel ? g_w2l : g_w1l);
    int p = blockIdx.x * 256 + threadIdx.x;  // pair index
    if (p < Dm * Dm / 2) {
        float a = w[2 * p], b = w[2 * p + 1];
        uint32_t h, l;
        split2(a, b, h, l);
        oh[p] = h;
        ol[p] = l;
    }
}

// ---------------- split+transpose feat: [b][d][n] -> bf16 [b][n][d] ----------
__global__ __launch_bounds__(256) void k_split_feat(const float* __restrict__ feat) {
    __shared__ float tile[64 * 65];
    int b = blockIdx.z, d0 = blockIdx.y * 64, n0 = blockIdx.x * 64;
    const float* src = feat + ((size_t)b * Dm + d0) * HW + n0;
    int tid = threadIdx.x;
#pragma unroll
    for (int it = 0; it < 4; it++) {
        int lin = it * 256 + tid;
        int r = lin >> 4, c4 = lin & 15;
        float4 v = *(const float4*)(src + (size_t)r * HW + c4 * 4);
        tile[r * 65 + c4 * 4 + 0] = v.x;
        tile[r * 65 + c4 * 4 + 1] = v.y;
        tile[r * 65 + c4 * 4 + 2] = v.z;
        tile[r * 65 + c4 * 4 + 3] = v.w;
    }
    __syncthreads();
    uint32_t* oh = (uint32_t*)g_fh;
    uint32_t* ol = (uint32_t*)g_fl;
#pragma unroll
    for (int it = 0; it < 8; it++) {
        int lin = it * 256 + tid;
        int n = lin >> 5, c = lin & 31;  // c = d-pair
        float v0 = tile[(2 * c) * 65 + n];
        float v1 = tile[(2 * c + 1) * 65 + n];
        uint32_t h, l;
        split2(v0, v1, h, l);
        size_t o = (((size_t)b * HW + n0 + n) * 256 + d0) / 2 + c;
        oh[o] = h;
        ol[o] = l;
    }
}

// ---------------- bn+relu+split: g_x -> g_xh/g_xl ----------------------------
__global__ __launch_bounds__(256) void k_bnsplit() {
    __shared__ float scs[256], scc[256];
    int tid = threadIdx.x;
    scs[tid] = g_s[tid];
    scc[tid] = g_c[tid];
    __syncthreads();
    size_t row = (size_t)blockIdx.x * 8 + (tid >> 5);
    int d0 = (tid & 31) * 8;
    const float* src = g_x + row * 256 + d0;
    float4 a = *(const float4*)src, b4 = *(const float4*)(src + 4);
    float v[8] = {a.x, a.y, a.z, a.w, b4.x, b4.y, b4.z, b4.w};
#pragma unroll
    for (int j = 0; j < 8; j++) v[j] = fmaxf(fmaf(scs[d0 + j], v[j], scc[d0 + j]), 0.f);
    uint32_t H[4], L[4];
#pragma unroll
    for (int j = 0; j < 4; j++) split2(v[2 * j], v[2 * j + 1], H[j], L[j]);
    size_t o = row * 128 + d0 / 2;
    *(uint4*)&((uint32_t*)g_xh)[o] = make_uint4(H[0], H[1], H[2], H[3]);
    *(uint4*)&((uint32_t*)g_xl)[o] = make_uint4(L[0], L[1], L[2], L[3]);
}

// ---------------- pure-bf16 HMMA GEMM: C[e,n] = sum_d A[e,d]*B[n,d] + bias ---
// cp.async depth-2 pipeline, K-chunk 32 -> 85.5 KB smem -> 2 CTAs/SM.
#define ROWW 20                 // words per padded row (32 halves + 8 pad)
#define MATW (128 * ROWW)       // 2560 words per matrix
#define STAGEW (4 * MATW)       // Ah,Al,Bh,Bl per stage = 10240 words
#define OFF_EXT (2 * STAGEW)    // 20480 words
#define GEMM_SMEM ((OFF_EXT + 1408) * 4)  // 87552 bytes
#define NCH 8                   // K chunks of 32

template <bool APPLY>
__global__ __launch_bounds__(256, 2) void k_gemm_mma(const float* __restrict__ bias) {
    extern __shared__ __align__(16) char smraw[];
    uint32_t* smw = (uint32_t*)smraw;
    float* ext = (float*)smraw + OFF_EXT;
    float* bsm = ext;        // [128]
    float* m1f = ext + 128;  // [128]
    float* m0f = ext + 256;  // [128]
    float* red = ext + 384;  // [2][128][4]
    const uint32_t sb = (uint32_t)__cvta_generic_to_shared(smraw);

    const int tid = threadIdx.x, lane = tid & 31, wid = tid >> 5;
    const int warp_m = wid >> 2, warp_n = wid & 3;
    const int bx = blockIdx.x, mb = blockIdx.y, bb = blockIdx.z;
    const int nb = bx * 128;

    if (tid < 128) bsm[tid] = bias[mb * 128 + tid];
    if (APPLY && tid < 128) {
        m1f[tid] = (float)g_m1[bb * HW + nb + tid];
        m0f[tid] = (float)g_m0[bb * HW + nb + tid];
    }

    const __nv_bfloat16* WH = APPLY ? g_w2h : g_w1h;
    const __nv_bfloat16* WL = APPLY ? g_w2l : g_w1l;
    const __nv_bfloat16* BH = (APPLY ? g_xh : g_fh) + (size_t)bb * HW * 256;
    const __nv_bfloat16* BL = (APPLY ? g_xl : g_fl) + (size_t)bb * HW * 256;

    float acc[4][4][4];
#pragma unroll
    for (int i = 0; i < 4; i++)
#pragma unroll
        for (int j = 0; j < 4; j++)
#pragma unroll
            for (int k = 0; k < 4; k++) acc[i][j][k] = 0.f;

    const int rA = lane >> 2, cA = lane & 3;

    auto issue = [&](int kc, int stage) {
        const int d0 = kc * 32;
        uint32_t base = sb + stage * STAGEW * 4;
        // each matrix: 128 rows x 32 halves = 512 CP16; 2 per thread per matrix
#pragma unroll
        for (int it = 0; it < 2; it++) {
            int lin = it * 256 + tid;
            int r = lin >> 2, c = lin & 3;  // c: 8-half group
            uint32_t doff = (r * ROWW + c * 4) * 4;
            size_t aoff = ((size_t)(mb * 128 + r) * 256 + d0 + c * 8);
            size_t boff = ((size_t)(nb + r) * 256 + d0 + c * 8);
            CP16(base + doff, (const char*)WH + aoff * 2);
            CP16(base + MATW * 4 + doff, (const char*)WL + aoff * 2);
            CP16(base + 2 * MATW * 4 + doff, (const char*)BH + boff * 2);
            CP16(base + 3 * MATW * 4 + doff, (const char*)BL + boff * 2);
        }
        CP_COMMIT();
    };

    issue(0, 0);
    issue(1, 1);

#pragma unroll 1
    for (int kc = 0; kc < NCH; kc++) {
        const int stage = kc & 1;
        if (kc < NCH - 1) CP_WAIT1(); else CP_WAIT0();
        __syncthreads();
        const uint32_t* Ah = smw + stage * STAGEW;
        const uint32_t* Al = Ah + MATW;
        const uint32_t* Bh = Al + MATW;
        const uint32_t* Bl = Bh + MATW;
#pragma unroll
        for (int kt = 0; kt < 2; kt++) {
            uint32_t Afh[4][4], Afl[4][4];
#pragma unroll
            for (int mt = 0; mt < 4; mt++) {
                int base = (warp_m * 64 + mt * 16 + rA) * ROWW + kt * 8 + cA;
                Afh[mt][0] = Ah[base];
                Afh[mt][1] = Ah[base + 8 * ROWW];
                Afh[mt][2] = Ah[base + 4];
                Afh[mt][3] = Ah[base + 8 * ROWW + 4];
                Afl[mt][0] = Al[base];
                Afl[mt][1] = Al[base + 8 * ROWW];
                Afl[mt][2] = Al[base + 4];
                Afl[mt][3] = Al[base + 8 * ROWW + 4];
            }
#pragma unroll
            for (int nt = 0; nt < 4; nt++) {
                int bbase = (warp_n * 32 + nt * 8 + rA) * ROWW + kt * 8 + cA;
                uint32_t bh0 = Bh[bbase], bh1 = Bh[bbase + 4];
                uint32_t bl0 = Bl[bbase], bl1 = Bl[bbase + 4];
#pragma unroll
                for (int mt = 0; mt < 4; mt++) {
                    mma16816(acc[mt][nt], Afh[mt], bh0, bh1);
                    mma16816(acc[mt][nt], Afh[mt], bl0, bl1);
                    mma16816(acc[mt][nt], Afl[mt], bh0, bh1);
                }
            }
        }
        __syncthreads();
        if (kc + 2 < NCH) issue(kc + 2, stage);
    }

    // ---- epilogue ----
    float* outb = (APPLY ? g_proj : g_x) + (size_t)bb * HW * 256;
#pragma unroll
    for (int mt = 0; mt < 4; mt++) {
#pragma unroll
        for (int h = 0; h < 2; h++) {
            int e_local = warp_m * 64 + mt * 16 + rA + h * 8;
            int e = mb * 128 + e_local;
            float bv = bsm[e_local];
            float s0 = 0.f, s1 = 0.f;
#pragma unroll
            for (int nt = 0; nt < 4; nt++) {
                int nc = warp_n * 32 + nt * 8 + cA * 2;
                float v0 = acc[mt][nt][h * 2 + 0] + bv;
                float v1 = acc[mt][nt][h * 2 + 1] + bv;
                outb[(size_t)(nb + nc) * 256 + e] = v0;
                outb[(size_t)(nb + nc + 1) * 256 + e] = v1;
                if (!APPLY) {
                    s0 += v0 + v1;
                    s1 += v0 * v0 + v1 * v1;
                } else {
                    s0 += m1f[nc] * v0 + m1f[nc + 1] * v1;
                    s1 += m0f[nc] * v0 + m0f[nc + 1] * v1;
                }
            }
            s0 += __shfl_down_sync(0xffffffffu, s0, 1, 4);
            s0 += __shfl_down_sync(0xffffffffu, s0, 2, 4);
            s1 += __shfl_down_sync(0xffffffffu, s1, 1, 4);
            s1 += __shfl_down_sync(0xffffffffu, s1, 2, 4);
            if (cA == 0) {
                red[(0 * 128 + e_local) * 4 + warp_n] = s0;
                red[(1 * 128 + e_local) * 4 + warp_n] = s1;
            }
        }
    }
    __syncthreads();
    {
        int q = tid >> 7, e_local = tid & 127;
        int e = mb * 128 + e_local;
        const float* r4 = &red[(q * 128 + e_local) * 4];
        float s = r4[0] + r4[1] + r4[2] + r4[3];
        if (!APPLY) {
            if (q == 0)
                g_ps[(size_t)e * 512 + bb * 128 + bx] = s;
            else
                g_pq[(size_t)e * 512 + bb * 128 + bx] = s;
        } else {
            if (q == 0)
                g_pfg[(size_t)(bb * Dm + e) * NBLK + bx] = s;
            else
                g_pbg[(size_t)(bb * Dm + e) * NBLK + bx] = s;
        }
    }
}

// ---------------- finalize BN stats ------------------------------------------
__global__ __launch_bounds__(128) void k_finstats(const float* __restrict__ gamma,
                                                  const float* __restrict__ beta) {
    __shared__ float shs[4], shq[4];
    int e = blockIdx.x, t = threadIdx.x, lane = t & 31, wp = t >> 5;
    float s = 0.f, q = 0.f;
    for (int i = t; i < 512; i += 128) {
        s += g_ps[e * 512 + i];
        q += g_pq[e * 512 + i];
    }
#pragma unroll
    for (int off = 16; off; off >>= 1) {
        s += __shfl_down_sync(0xffffffffu, s, off);
        q += __shfl_down_sync(0xffffffffu, q, off);
    }
    if (lane == 0) {
        shs[wp] = s;
        shq[wp] = q;
    }
    __syncthreads();
    if (t == 0) {
        float ts = shs[0] + shs[1] + shs[2] + shs[3];
        float tq = shq[0] + shq[1] + shq[2] + shq[3];
        const float inv_n = 1.f / (float)(Bm * HW);
        float mean = ts * inv_n;
        float var = fmaxf(tq * inv_n - mean * mean, 0.f);
        float sc = gamma[e] / sqrtf(var + 1e-5f);
        g_s[e] = sc;
        g_c[e] = beta[e] - mean * sc;
    }
}

// ---------------- finalize prototypes ----------------------------------------
__global__ __launch_bounds__(128) void k_finproto() {
    __shared__ float shf[4], shb[4];
    int e = blockIdx.x, b = blockIdx.y, t = threadIdx.x, lane = t & 31, wp = t >> 5;
    float f = g_pfg[(b * Dm + e) * NBLK + t];
    float g = g_pbg[(b * Dm + e) * NBLK + t];
#pragma unroll
    for (int off = 16; off; off >>= 1) {
        f += __shfl_down_sync(0xffffffffu, f, off);
        g += __shfl_down_sync(0xffffffffu, g, off);
    }
    if (lane == 0) {
        shf[wp] = f;
        shb[wp] = g;
    }
    __syncthreads();
    if (t == 0) {
        g_mfg[b * Dm + e] = shf[0] + shf[1] + shf[2] + shf[3];
        g_mbg[b * Dm + e] = shb[0] + shb[1] + shb[2] + shb[3];
    }
}

// ---------------- pair loss ---------------------------------------------------
struct PairSmem {
    unsigned short listA[HW];
    unsigned short listN[HW];
    unsigned long long sbuf[4096];
    float qs[32 * 257];
    float vbuf[8][264];
    int hist[256];
    float red[34];
    int redi[34];
    float warpP[8][33];
    float warpN[8][33];
    int aidx[32];
    float aflag[32];
    int cidx[128];
    float cflag[128];
    int pidx[64];
    float pflag[64];
    int nidx[64];
    float nflag[64];
    int cntA, cntN, coll, bstar;
    float bestv;
    int besti;
};

__device__ __forceinline__ void pair_argmax(PairSmem* S, float v, int i, int tid) {
    int lane = tid & 31, w = tid >> 5;
#pragma unroll
    for (int off = 16; off; off >>= 1) {
        float ov = __shfl_down_sync(0xffffffffu, v, off);
        int oi = __shfl_down_sync(0xffffffffu, i, off);
        if (ov > v || (ov == v && oi < i)) { v = ov; i = oi; }
    }
    if (lane == 0) { S->red[w] = v; S->redi[w] = i; }
    __syncthreads();
    if (w == 0) {
        v = (lane < 8) ? S->red[lane] : -FLT_MAX;
        i = (lane < 8) ? S->redi[lane] : 0x7FFFFFFF;
#pragma unroll
        for (int off = 4; off; off >>= 1) {
            float ov = __shfl_down_sync(0xffffffffu, v, off);
            int oi = __shfl_down_sync(0xffffffffu, i, off);
            if (ov > v || (ov == v && oi < i)) { v = ov; i = oi; }
        }
        if (lane == 0) { S->bestv = v; S->besti = i; }
    }
    __syncthreads();
}

__device__ void select_topk(PairSmem* S, const unsigned short* list, int cnt,
                            const float* __restrict__ key, int K, int* oidx, float* oflag,
                            int tid) {
    float lastv = FLT_MAX;
    int lasti = -1;
    for (int kk = 0; kk < K; kk++) {
        float bv = -FLT_MAX;
        int bi = 0x7FFFFFFF;
        for (int ii = tid; ii < cnt; ii += 256) {
            int idx = list[ii];
            float v = key[idx];
            if (v < lastv || (v == lastv && idx > lasti)) {
                if (v > bv || (v == bv && idx < bi)) { bv = v; bi = idx; }
            }
        }
        pair_argmax(S, bv, bi, tid);
        float gbv = S->bestv;
        int gbi = S->besti;
        if (gbv > -FLT_MAX) {
            lastv = gbv;
            lasti = gbi;
            if (tid == 0) { oidx[kk] = gbi; oflag[kk] = 1.f; }
        } else {
            lastv = -FLT_MAX;
            lasti = 0x7FFFFFFF;
            if (tid == 0) { oidx[kk] = 0; oflag[kk] = 0.f; }
        }
        __syncthreads();
    }
}

__device__ void bitonic_desc(PairSmem* S, int n, int tid) {
    for (int k = 2; k <= n; k <<= 1)
        for (int j = k >> 1; j > 0; j >>= 1) {
            for (int t = tid; t < n; t += 256) {
                int ixj = t ^ j;
                if (ixj > t) {
                    unsigned long long x = S->sbuf[t], y = S->sbuf[ixj];
                    bool desc = ((t & k) == 0);
                    if (desc ? (x < y) : (x > y)) {
                        S->sbuf[t] = y;
                        S->sbuf[ixj] = x;
                    }
                }
            }
            __syncthreads();
        }
}

__device__ void radix_select(PairSmem* S, const unsigned short* list, int cnt,
                             const float* __restrict__ key, int K, int* oidx, float* oflag,
                             int tid) {
    int target = min(K, cnt);
    if (target == 0) {
        for (int kk = tid; kk < K; kk += 256) { oidx[kk] = 0; oflag[kk] = 0.f; }
        __syncthreads();
        return;
    }
    S->hist[tid] = 0;
    __syncthreads();
    for (int ii = tid; ii < cnt; ii += 256) {
        float r = key[list[ii]];
        int b = (int)(r * 256.f);
        b = b < 0 ? 0 : (b > 255 ? 255 : b);
        atomicAdd(&S->hist[b], 1);
    }
    __syncthreads();
    if (tid == 0) {
        int acc = 0, bs = 0;
        for (int b = 255; b >= 0; b--) {
            acc += S->hist[b];
            if (acc >= target) { bs = b; break; }
        }
        S->bstar = bs;
        S->coll = 0;
    }
    __syncthreads();
    int bstar = S->bstar;
    for (int ii = tid; ii < cnt; ii += 256) {
        int idx = list[ii];
        float r = key[idx];
        int b = (int)(r * 256.f);
        b = b < 0 ? 0 : (b > 255 ? 255 : b);
        if (b >= bstar) {
            int p = atomicAdd(&S->coll, 1);
            if (p < 4096)
                S->sbuf[p] = ((unsigned long long)__float_as_uint(r) << 32) |
                             (unsigned long long)(unsigned int)(~(unsigned int)idx);
        }
    }
    __syncthreads();
    int coll = S->coll;
    if (coll > 4096) {
        select_topk(S, list, cnt, key, K, oidx, oflag, tid);
        return;
    }
    int n = 1;
    while (n < coll) n <<= 1;
    for (int i = coll + tid; i < n; i += 256) S->sbuf[i] = 0ull;
    __syncthreads();
    bitonic_desc(S, n, tid);
    for (int kk = tid; kk < K; kk += 256) {
        if (kk < target) {
            oidx[kk] = (int)(~(unsigned int)(S->sbuf[kk] & 0xFFFFFFFFull));
            oflag[kk] = 1.f;
        } else {
            oidx[kk] = 0;
            oflag[kk] = 0.f;
        }
    }
    __syncthreads();
}

__device__ void hard_select(PairSmem* S, const float* __restrict__ ub, int* oidx, float* oflag,
                            int tid) {
    if (tid < 128) {
        unsigned long long kv;
        if (S->cflag[tid] != 0.f) {
            unsigned int u = __float_as_uint(ub[S->cidx[tid]]) + 1u;
            kv = ((unsigned long long)u << 32) |
                 (unsigned long long)(unsigned int)(~(unsigned int)tid);
        } else {
            kv = (unsigned long long)(unsigned int)(~(unsigned int)tid);
        }
        S->sbuf[tid] = kv;
    }
    __syncthreads();
    bitonic_desc(S, 128, tid);
    if (tid < 64) {
        int t = (int)((~(unsigned int)(S->sbuf[tid] & 0xFFFFFFFFull)) & 127u);
        oidx[tid] = S->cidx[t];
        oflag[tid] = S->cflag[t];
    }
    __syncthreads();
}

__global__ __launch_bounds__(256) void k_pair(const float* __restrict__ unc,
                                              const float* __restrict__ r_anc,
                                              const float* __restrict__ r_pos,
                                              const float* __restrict__ r_neg) {
    extern __shared__ char smraw[];
    PairSmem* S = (PairSmem*)smraw;
    int task = blockIdx.x;
    int b = task >> 1, c = task & 1;
    int tid = threadIdx.x, w = tid >> 5, l = tid & 31;
    const unsigned char* am = (c == 0 ? g_m1 : g_m0) + b * HW;
    const unsigned char* nm = (c == 0 ? g_m0 : g_m1) + b * HW;

    if (tid == 0) { S->cntA = 0; S->cntN = 0; }
    __syncthreads();
    for (int i = tid; i < HW; i += 256) {
        if (am[i]) { int p = atomicAdd(&S->cntA, 1); S->listA[p] = (unsigned short)i; }
        if (nm[i]) { int p = atomicAdd(&S->cntN, 1); S->listN[p] = (unsigned short)i; }
    }
    __syncthreads();
    int cntA = S->cntA, cntN = S->cntN;

    const float* ra = r_anc + ((size_t)b * 2 + c) * HW;
    const float* rp = r_pos + ((size_t)b * 2 + c) * HW;
    const float* rn = r_neg + ((size_t)b * 2 + c) * HW;
    const float* ub = unc + (size_t)b * HW;

    radix_select(S, S->listA, cntA, ra, 32, S->aidx, S->aflag, tid);
    radix_select(S, S->listA, cntA, rp, 128, S->cidx, S->cflag, tid);
    hard_select(S, ub, S->pidx, S->pflag, tid);
    radix_select(S, S->listN, cntN, rn, 128, S->cidx, S->cflag, tid);
    hard_select(S, ub, S->nidx, S->nflag, tid);

    const float* projb = g_proj + (size_t)b * HW * 256;

    for (int q = 0; q < 4; q++) {
        int a = w * 4 + q;
        const float* src = projb + (size_t)S->aidx[a] * 256;
        float v[8], ss = 0.f;
#pragma unroll
        for (int cc = 0; cc < 8; cc++) {
            v[cc] = src[l + 32 * cc];
            ss = fmaf(v[cc], v[cc], ss);
        }
#pragma unroll
        for (int off = 16; off; off >>= 1) ss += __shfl_xor_sync(0xffffffffu, ss, off);
        float sc = 1.f / fmaxf(sqrtf(ss), 1e-12f);
#pragma unroll
        for (int cc = 0; cc < 8; cc++) S->qs[a * 257 + l + 32 * cc] = v[cc] * sc;
    }
    __syncthreads();

    float accP = 0.f, accN = 0.f;
    for (int s = w; s < 128; s += 8) {
        int si = s & 63;
        bool isP = s < 64;
        float fl = isP ? S->pflag[si] : S->nflag[si];
        if (fl != 0.f) {
            int idx = isP ? S->pidx[si] : S->nidx[si];
            const float* src = projb + (size_t)idx * 256;
            float v[8], ss = 0.f;
#pragma unroll
            for (int cc = 0; cc < 8; cc++) {
                v[cc] = src[l + 32 * cc];
                ss = fmaf(v[cc], v[cc], ss);
            }
#pragma unroll
            for (int off = 16; off; off >>= 1) ss += __shfl_xor_sync(0xffffffffu, ss, off);
            float sc = 1.f / fmaxf(sqrtf(ss), 1e-12f);
#pragma unroll
            for (int cc = 0; cc < 8; cc++) S->vbuf[w][l + 32 * cc] = v[cc] * sc;
            __syncwarp();
            float dot = 0.f;
            const float* qrow = &S->qs[l * 257];
#pragma unroll 8
            for (int d = 0; d < 256; d++) dot = fmaf(qrow[d], S->vbuf[w][d], dot);
            float ev = expf(dot * 10.f);
            if (isP) accP += ev; else accN += ev;
            __syncwarp();
        }
    }
    S->warpP[w][l] = accP;
    S->warpN[w][l] = accN;
    __syncthreads();

    if (w == 0) {
        float p = 0.f, n = 0.f;
#pragma unroll
        for (int ww = 0; ww < 8; ww++) {
            p += S->warpP[ww][l];
            n += S->warpN[ww][l];
        }
        bool inc = (cntA >= 1) && (cntN >= 1);
        if (!inc) p += 1.f;
        float per = -logf(p / (p + n + 1e-8f));
        float af = S->aflag[l];
        float ws = per * af, as = af;
#pragma unroll
        for (int off = 16; off; off >>= 1) {
            ws += __shfl_down_sync(0xffffffffu, ws, off);
            as += __shfl_down_sync(0xffffffffu, as, off);
        }
        if (l == 0) {
            g_bl[task] = inc ? (ws / fmaxf(as, 1.f)) : 0.f;
            g_inc[task] = inc ? 1 : 0;
        }
    }
}

// ---------------- final: local + global loss ---------------------------------
__global__ __launch_bounds__(256) void k_final(float* __restrict__ out, int out_size) {
    __shared__ float scratch[34];
    __shared__ float qf[4][257], qb[4][257];
    __shared__ float cf[4], cb[4];
    __shared__ float pfv[4], pbv[4], nfv[4], nbv[4];
    int tid = threadIdx.x;

    for (int b = 0; b < 4; b++) {
        float c1 = 0.f, c0 = 0.f;
        for (int i = tid; i < HW; i += 256) {
            c1 += (float)g_m1[b * HW + i];
            c0 += (float)g_m0[b * HW + i];
        }
        float s1 = blk_sum(scratch, c1, tid);
        float s0 = blk_sum(scratch, c0, tid);
        if (tid == 0) { cf[b] = s1; cb[b] = s0; }
    }
    __syncthreads();

    for (int b = 0; b < 4; b++) {
        float mf = g_mfg[b * Dm + tid] / fmaxf(cf[b], 1.f);
        float mb_ = g_mbg[b * Dm + tid] / fmaxf(cb[b], 1.f);
        float ssf = blk_sum(scratch, mf * mf, tid);
        qf[b][tid] = mf / fmaxf(sqrtf(ssf), 1e-12f);
        float ssb = blk_sum(scratch, mb_ * mb_, tid);
        qb[b][tid] = mb_ / fmaxf(sqrtf(ssb), 1e-12f);
    }
    __syncthreads();

    for (int b = 0; b < 4; b++) {
        float d1 = blk_sum(scratch, qf[b][tid] * qf[b][tid], tid);
        float d2 = blk_sum(scratch, qb[b][tid] * qb[b][tid], tid);
        if (tid == 0) {
            pfv[b] = expf(d1 * 10.f);
            pbv[b] = expf(d2 * 10.f);
            nfv[b] = 0.f;
            nbv[b] = 0.f;
        }
        __syncthreads();
    }
    for (int b = 0; b < 4; b++) {
        for (int j = 0; j <= b; j++) {
            float dqbqf = blk_sum(scratch, qb[j][tid] * qf[b][tid], tid);
            float dqfqb = blk_sum(scratch, qf[j][tid] * qb[b][tid], tid);
            if (tid == 0) {
                bool vgj = (cf[j] >= 1.f) && (cb[j] >= 1.f);
                if (vgj) {
                    nfv[b] += expf(dqbqf * 10.f);
                    nbv[b] += expf(dqfqb * 10.f);
                }
            }
            __syncthreads();
        }
    }

    if (tid == 0) {
        float lsum = 0.f;
        int icnt = 0;
        for (int t = 0; t < 8; t++) {
            lsum += g_bl[t];
            icnt += g_inc[t];
        }
        float l_local = lsum / (float)max(icnt, 1);
        float gs = 0.f;
        int vcnt = 0;
        for (int b = 0; b < 4; b++) {
            bool vg = (cf[b] >= 1.f) && (cb[b] >= 1.f);
            if (vg) {
                float lg = -logf(pfv[b] / (pfv[b] + nfv[b] + 1e-8f)) -
                           logf(pbv[b] / (pbv[b] + nbv[b] + 1e-8f));
                gs += lg;
                vcnt++;
            }
        }
        float l_global = gs / (float)max(vcnt, 1);
        if (out_size > 0) out[0] = l_local + 0.5f * l_global;
        if (out_size > 1) out[1] = l_local;
        if (out_size > 2) out[2] = l_global;
    }
}

// ---------------- launch ------------------------------------------------------
extern "C" void kernel_launch(void* const* d_in, const int* in_sizes, int n_in, void* d_out,
                              int out_size) {
    const float* feat = (const float*)d_in[0];
    const int* labels = (const int*)d_in[1];
    const float* prob_ori = (const float*)d_in[2];
    const float* prob_aug = (const float*)d_in[3];
    const float* unc = (const float*)d_in[4];
    const float* r_anc = (const float*)d_in[5];
    const float* r_pos = (const float*)d_in[6];
    const float* r_neg = (const float*)d_in[7];
    const float* w1 = (const float*)d_in[8];
    const float* b1 = (const float*)d_in[9];
    const float* gamma = (const float*)d_in[10];
    const float* beta = (const float*)d_in[11];
    const float* w2 = (const float*)d_in[12];
    const float* b2 = (const float*)d_in[13];

    cudaFuncSetAttribute(k_gemm_mma<false>, cudaFuncAttributeMaxDynamicSharedMemorySize,
                         GEMM_SMEM);
    cudaFuncSetAttribute(k_gemm_mma<true>, cudaFuncAttributeMaxDynamicSharedMemorySize,
                         GEMM_SMEM);
    cudaFuncSetAttribute(k_pair, cudaFuncAttributeMaxDynamicSharedMemorySize,
                         (int)sizeof(PairSmem));

    k_masks<<<(Bm * HW + 255) / 256, 256>>>(prob_ori, prob_aug, unc, labels);
    k_splitw<<<dim3(Dm * Dm / 2 / 256, 2), 256>>>(w1, w2);
    k_split_feat<<<dim3(HW / 64, Dm / 64, Bm), 256>>>(feat);
    dim3 gg(NBLK, 2, Bm);
    k_gemm_mma<false><<<gg, 256, GEMM_SMEM>>>(b1);
    k_finstats<<<Dm, 128>>>(gamma, beta);
    k_bnsplit<<<Bm * HW / 8, 256>>>();
    k_gemm_mma<true><<<gg, 256, GEMM_SMEM>>>(b2);
    k_finproto<<<dim3(Dm, Bm), 128>>>();
    k_pair<<<8, 256, sizeof(PairSmem)>>>(unc, r_anc, r_pos, r_neg);
    k_final<<<1, 256>>>((float*)d_out, out_size);
}

// round 9
// speedup vs baseline: 1.4257x; 1.2322x over previous
#include <cuda_runtime.h>
#include <cuda_bf16.h>
#include <float.h>
#include <math.h>
#include <stdint.h>

#define HW 16384
#define Dm 256
#define Bm 4
#define NBLK 128

// ---------------- scratch ----------------------------------------------------
__device__ float g_x[Bm * HW * Dm];
__device__ float g_proj[Bm * HW * Dm];
__device__ __nv_bfloat16 g_fh[Bm * HW * Dm];
__device__ __nv_bfloat16 g_fl[Bm * HW * Dm];
__device__ __nv_bfloat16 g_xh[Bm * HW * Dm];
__device__ __nv_bfloat16 g_xl[Bm * HW * Dm];
__device__ __nv_bfloat16 g_w1h[Dm * Dm], g_w1l[Dm * Dm];
__device__ __nv_bfloat16 g_w2h[Dm * Dm], g_w2l[Dm * Dm];
__device__ float g_s[Dm];
__device__ float g_c[Dm];
__device__ unsigned char g_m1[Bm * HW];
__device__ unsigned char g_m0[Bm * HW];
__device__ float g_ps[Dm * 512];
__device__ float g_pq[Dm * 512];
__device__ float g_pfg[Bm * Dm * NBLK];
__device__ float g_pbg[Bm * Dm * NBLK];
__device__ float g_mfg[Bm * Dm];
__device__ float g_mbg[Bm * Dm];
// selection outputs
__device__ int g_aidx[8 * 32];
__device__ float g_aflag[8 * 32];
__device__ int g_pidx[8 * 64];
__device__ float g_pflag[8 * 64];
__device__ int g_nidx[8 * 64];
__device__ float g_nflag[8 * 64];
__device__ int g_cA[8], g_cB[8];
__device__ float g_dacc[8 * 4 * 32];

// ---------------- block reduction --------------------------------------------
__device__ __forceinline__ float blk_sum(volatile float* scratch, float v, int tid) {
    int lane = tid & 31, w = tid >> 5;
#pragma unroll
    for (int off = 16; off; off >>= 1) v += __shfl_down_sync(0xffffffffu, v, off);
    if (lane == 0) scratch[w] = v;
    __syncthreads();
    if (w == 0) {
        v = (lane < 8) ? scratch[lane] : 0.f;
#pragma unroll
        for (int off = 4; off; off >>= 1) v += __shfl_down_sync(0xffffffffu, v, off);
        if (lane == 0) scratch[32] = v;
    }
    __syncthreads();
    return scratch[32];
}

// ---------------- masks ------------------------------------------------------
__global__ void k_masks(const float* __restrict__ prob_ori, const float* __restrict__ prob_aug,
                        const float* __restrict__ unc, const int* __restrict__ labels) {
    int idx = blockIdx.x * blockDim.x + threadIdx.x;
    if (idx >= Bm * HW) return;
    int b = idx >> 14;
    int hw = idx & (HW - 1);
    const float* po = prob_ori + (size_t)b * 2 * HW;
    const float* pa = prob_aug + (size_t)b * 2 * HW;
    int io = po[HW + hw] > po[hw];
    int ia = pa[HW + hw] > pa[hw];
    bool rel = (io == ia);
    bool diff = unc[idx] > 0.5f;
    int lab = labels[idx];
    bool valid = rel && diff;
    g_m1[idx] = (unsigned char)(valid && lab == 1);
    g_m0[idx] = (unsigned char)(valid && lab == 0);
}

// ---------------- bf16 hi/lo split -------------------------------------------
__device__ __forceinline__ void split2(float a, float b, uint32_t& h, uint32_t& l) {
    __nv_bfloat16 ah = __float2bfloat16_rn(a), bh = __float2bfloat16_rn(b);
    float ar = a - __bfloat162float(ah), br = b - __bfloat162float(bh);
    __nv_bfloat16 al = __float2bfloat16_rn(ar), bl = __float2bfloat16_rn(br);
    h = (uint32_t)*(unsigned short*)&ah | ((uint32_t)*(unsigned short*)&bh << 16);
    l = (uint32_t)*(unsigned short*)&al | ((uint32_t)*(unsigned short*)&bl << 16);
}

__device__ __forceinline__ void mma16816(float* c, const uint32_t* a, uint32_t b0, uint32_t b1) {
    asm volatile(
        "mma.sync.aligned.m16n8k16.row.col.f32.bf16.bf16.f32 "
        "{%0,%1,%2,%3}, {%4,%5,%6,%7}, {%8,%9}, {%0,%1,%2,%3};"
        : "+f"(c[0]), "+f"(c[1]), "+f"(c[2]), "+f"(c[3])
        : "r"(a[0]), "r"(a[1]), "r"(a[2]), "r"(a[3]), "r"(b0), "r"(b1));
}

#define CP16(dst_u32, src_ptr) \
    asm volatile("cp.async.cg.shared.global [%0], [%1], 16;" ::"r"(dst_u32), "l"(src_ptr))
#define CP_COMMIT() asm volatile("cp.async.commit_group;" ::: "memory")
#define CP_WAIT1() asm volatile("cp.async.wait_group 1;" ::: "memory")
#define CP_WAIT0() asm volatile("cp.async.wait_group 0;" ::: "memory")

// ---------------- split weights ----------------------------------------------
__global__ __launch_bounds__(256) void k_splitw(const float* __restrict__ w1,
                                                const float* __restrict__ w2) {
    int sel = blockIdx.y;
    const float* w = sel ? w2 : w1;
    uint32_t* oh = (uint32_t*)(sel ? g_w2h : g_w1h);
    uint32_t* ol = (uint32_t*)(sel ? g_w2l : g_w1l);
    int p = blockIdx.x * 256 + threadIdx.x;
    if (p < Dm * Dm / 2) {
        float a = w[2 * p], b = w[2 * p + 1];
        uint32_t h, l;
        split2(a, b, h, l);
        oh[p] = h;
        ol[p] = l;
    }
}

// ---------------- split+transpose feat ---------------------------------------
__global__ __launch_bounds__(256) void k_split_feat(const float* __restrict__ feat) {
    __shared__ float tile[64 * 65];
    int b = blockIdx.z, d0 = blockIdx.y * 64, n0 = blockIdx.x * 64;
    const float* src = feat + ((size_t)b * Dm + d0) * HW + n0;
    int tid = threadIdx.x;
#pragma unroll
    for (int it = 0; it < 4; it++) {
        int lin = it * 256 + tid;
        int r = lin >> 4, c4 = lin & 15;
        float4 v = *(const float4*)(src + (size_t)r * HW + c4 * 4);
        tile[r * 65 + c4 * 4 + 0] = v.x;
        tile[r * 65 + c4 * 4 + 1] = v.y;
        tile[r * 65 + c4 * 4 + 2] = v.z;
        tile[r * 65 + c4 * 4 + 3] = v.w;
    }
    __syncthreads();
    uint32_t* oh = (uint32_t*)g_fh;
    uint32_t* ol = (uint32_t*)g_fl;
#pragma unroll
    for (int it = 0; it < 8; it++) {
        int lin = it * 256 + tid;
        int n = lin >> 5, c = lin & 31;
        float v0 = tile[(2 * c) * 65 + n];
        float v1 = tile[(2 * c + 1) * 65 + n];
        uint32_t h, l;
        split2(v0, v1, h, l);
        size_t o = (((size_t)b * HW + n0 + n) * 256 + d0) / 2 + c;
        oh[o] = h;
        ol[o] = l;
    }
}

// ---------------- bn+relu+split ----------------------------------------------
__global__ __launch_bounds__(256) void k_bnsplit() {
    __shared__ float scs[256], scc[256];
    int tid = threadIdx.x;
    scs[tid] = g_s[tid];
    scc[tid] = g_c[tid];
    __syncthreads();
    size_t row = (size_t)blockIdx.x * 8 + (tid >> 5);
    int d0 = (tid & 31) * 8;
    const float* src = g_x + row * 256 + d0;
    float4 a = *(const float4*)src, b4 = *(const float4*)(src + 4);
    float v[8] = {a.x, a.y, a.z, a.w, b4.x, b4.y, b4.z, b4.w};
#pragma unroll
    for (int j = 0; j < 8; j++) v[j] = fmaxf(fmaf(scs[d0 + j], v[j], scc[d0 + j]), 0.f);
    uint32_t H[4], L[4];
#pragma unroll
    for (int j = 0; j < 4; j++) split2(v[2 * j], v[2 * j + 1], H[j], L[j]);
    size_t o = row * 128 + d0 / 2;
    *(uint4*)&((uint32_t*)g_xh)[o] = make_uint4(H[0], H[1], H[2], H[3]);
    *(uint4*)&((uint32_t*)g_xl)[o] = make_uint4(L[0], L[1], L[2], L[3]);
}

// ---------------- selection (smem struct + helpers) ---------------------------
struct PairS {
    unsigned short listA[HW];
    unsigned short listN[HW];
    unsigned long long sbuf[512];
    int hist[256];
    float red[34];
    int redi[34];
    int cidx[128];
    float cflag[128];
    int cntA, cntN, coll, bstar;
    float bestv;
    int besti;
};

__device__ __forceinline__ void pair_argmax(PairS* S, float v, int i, int tid) {
    int lane = tid & 31, w = tid >> 5;
#pragma unroll
    for (int off = 16; off; off >>= 1) {
        float ov = __shfl_down_sync(0xffffffffu, v, off);
        int oi = __shfl_down_sync(0xffffffffu, i, off);
        if (ov > v || (ov == v && oi < i)) { v = ov; i = oi; }
    }
    if (lane == 0) { S->red[w] = v; S->redi[w] = i; }
    __syncthreads();
    if (w == 0) {
        v = (lane < 8) ? S->red[lane] : -FLT_MAX;
        i = (lane < 8) ? S->redi[lane] : 0x7FFFFFFF;
#pragma unroll
        for (int off = 4; off; off >>= 1) {
            float ov = __shfl_down_sync(0xffffffffu, v, off);
            int oi = __shfl_down_sync(0xffffffffu, i, off);
            if (ov > v || (ov == v && oi < i)) { v = ov; i = oi; }
        }
        if (lane == 0) { S->bestv = v; S->besti = i; }
    }
    __syncthreads();
}

__device__ void select_topk(PairS* S, const unsigned short* list, int cnt,
                            const float* __restrict__ key, int K, int* oidx, float* oflag,
                            int tid) {
    float lastv = FLT_MAX;
    int lasti = -1;
    for (int kk = 0; kk < K; kk++) {
        float bv = -FLT_MAX;
        int bi = 0x7FFFFFFF;
        for (int ii = tid; ii < cnt; ii += 256) {
            int idx = list[ii];
            float v = key[idx];
            if (v < lastv || (v == lastv && idx > lasti)) {
                if (v > bv || (v == bv && idx < bi)) { bv = v; bi = idx; }
            }
        }
        pair_argmax(S, bv, bi, tid);
        float gbv = S->bestv;
        int gbi = S->besti;
        if (gbv > -FLT_MAX) {
            lastv = gbv;
            lasti = gbi;
            if (tid == 0) { oidx[kk] = gbi; oflag[kk] = 1.f; }
        } else {
            lastv = -FLT_MAX;
            lasti = 0x7FFFFFFF;
            if (tid == 0) { oidx[kk] = 0; oflag[kk] = 0.f; }
        }
        __syncthreads();
    }
}

__device__ void bitonic_desc(PairS* S, int n, int tid) {
    for (int k = 2; k <= n; k <<= 1)
        for (int j = k >> 1; j > 0; j >>= 1) {
            for (int t = tid; t < n; t += 256) {
                int ixj = t ^ j;
                if (ixj > t) {
                    unsigned long long x = S->sbuf[t], y = S->sbuf[ixj];
                    bool desc = ((t & k) == 0);
                    if (desc ? (x < y) : (x > y)) {
                        S->sbuf[t] = y;
                        S->sbuf[ixj] = x;
                    }
                }
            }
            __syncthreads();
        }
}

__device__ void radix_select(PairS* S, const unsigned short* list, int cnt,
                             const float* __restrict__ key, int K, int* oidx, float* oflag,
                             int tid) {
    int target = min(K, cnt);
    if (target == 0) {
        for (int kk = tid; kk < K; kk += 256) { oidx[kk] = 0; oflag[kk] = 0.f; }
        __syncthreads();
        return;
    }
    S->hist[tid] = 0;
    __syncthreads();
    for (int ii = tid; ii < cnt; ii += 256) {
        float r = key[list[ii]];
        int b = (int)(r * 256.f);
        b = b < 0 ? 0 : (b > 255 ? 255 : b);
        atomicAdd(&S->hist[b], 1);
    }
    __syncthreads();
    if (tid == 0) {
        int acc = 0, bs = 0;
        for (int b = 255; b >= 0; b--) {
            acc += S->hist[b];
            if (acc >= target) { bs = b; break; }
        }
        S->bstar = bs;
        S->coll = 0;
    }
    __syncthreads();
    int bstar = S->bstar;
    for (int ii = tid; ii < cnt; ii += 256) {
        int idx = list[ii];
        float r = key[idx];
        int b = (int)(r * 256.f);
        b = b < 0 ? 0 : (b > 255 ? 255 : b);
        if (b >= bstar) {
            int p = atomicAdd(&S->coll, 1);
            if (p < 512)
                S->sbuf[p] = ((unsigned long long)__float_as_uint(r) << 32) |
                             (unsigned long long)(unsigned int)(~(unsigned int)idx);
        }
    }
    __syncthreads();
    int coll = S->coll;
    if (coll > 512) {  // degenerate key distribution: exact fallback
        select_topk(S, list, cnt, key, K, oidx, oflag, tid);
        return;
    }
    int n = 1;
    while (n < coll) n <<= 1;
    for (int i = coll + tid; i < n; i += 256) S->sbuf[i] = 0ull;
    __syncthreads();
    bitonic_desc(S, n, tid);
    for (int kk = tid; kk < K; kk += 256) {
        if (kk < target) {
            oidx[kk] = (int)(~(unsigned int)(S->sbuf[kk] & 0xFFFFFFFFull));
            oflag[kk] = 1.f;
        } else {
            oidx[kk] = 0;
            oflag[kk] = 0.f;
        }
    }
    __syncthreads();
}

__device__ void hard_select(PairS* S, const float* __restrict__ ub, int* oidx, float* oflag,
                            int tid) {
    if (tid < 128) {
        unsigned long long kv;
        if (S->cflag[tid] != 0.f) {
            unsigned int u = __float_as_uint(ub[S->cidx[tid]]) + 1u;
            kv = ((unsigned long long)u << 32) |
                 (unsigned long long)(unsigned int)(~(unsigned int)tid);
        } else {
            kv = (unsigned long long)(unsigned int)(~(unsigned int)tid);
        }
        S->sbuf[tid] = kv;
    }
    __syncthreads();
    bitonic_desc(S, 128, tid);
    if (tid < 64) {
        int t = (int)((~(unsigned int)(S->sbuf[tid] & 0xFFFFFFFFull)) & 127u);
        oidx[tid] = S->cidx[t];
        oflag[tid] = S->cflag[t];
    }
    __syncthreads();
}

__device__ void do_select(char* smraw, int task, const float* unc, const float* r_anc,
                          const float* r_pos, const float* r_neg) {
    PairS* S = (PairS*)smraw;
    int b = task >> 1, c = task & 1;
    int tid = threadIdx.x;
    const unsigned char* am = (c == 0 ? g_m1 : g_m0) + b * HW;
    const unsigned char* nm = (c == 0 ? g_m0 : g_m1) + b * HW;

    if (tid == 0) { S->cntA = 0; S->cntN = 0; }
    __syncthreads();
    for (int i = tid; i < HW; i += 256) {
        if (am[i]) { int p = atomicAdd(&S->cntA, 1); S->listA[p] = (unsigned short)i; }
        if (nm[i]) { int p = atomicAdd(&S->cntN, 1); S->listN[p] = (unsigned short)i; }
    }
    __syncthreads();
    int cntA = S->cntA, cntN = S->cntN;

    const float* ra = r_anc + ((size_t)b * 2 + c) * HW;
    const float* rp = r_pos + ((size_t)b * 2 + c) * HW;
    const float* rn = r_neg + ((size_t)b * 2 + c) * HW;
    const float* ub = unc + (size_t)b * HW;

    radix_select(S, S->listA, cntA, ra, 32, g_aidx + task * 32, g_aflag + task * 32, tid);
    radix_select(S, S->listA, cntA, rp, 128, S->cidx, S->cflag, tid);
    hard_select(S, ub, g_pidx + task * 64, g_pflag + task * 64, tid);
    radix_select(S, S->listN, cntN, rn, 128, S->cidx, S->cflag, tid);
    hard_select(S, ub, g_nidx + task * 64, g_nflag + task * 64, tid);

    if (tid == 0) {
        g_cA[task] = cntA;
        g_cB[task] = cntN;
    }
}

// ---------------- pure-bf16 HMMA GEMM ----------------------------------------
#define ROWW 20
#define MATW (128 * ROWW)
#define STAGEW (4 * MATW)
#define OFF_EXT (2 * STAGEW)
#define GEMM_SMEM ((OFF_EXT + 1408) * 4)  // 87552 bytes
#define NCH 8

template <bool APPLY>
__global__ __launch_bounds__(256, 2) void k_gemm_mma(const float* __restrict__ bias,
                                                     const float* __restrict__ unc,
                                                     const float* __restrict__ r_anc,
                                                     const float* __restrict__ r_pos,
                                                     const float* __restrict__ r_neg) {
    extern __shared__ __align__(16) char smraw[];
    int Bl = blockIdx.x;
    if (!APPLY) {
        if (Bl < 8) {
            do_select(smraw, Bl, unc, r_anc, r_pos, r_neg);
            return;
        }
        Bl -= 8;
    }
    const int bx = Bl & 127, mb = (Bl >> 7) & 1, bb = Bl >> 8;

    uint32_t* smw = (uint32_t*)smraw;
    float* ext = (float*)smraw + OFF_EXT;
    float* bsm = ext;
    float* m1f = ext + 128;
    float* m0f = ext + 256;
    float* red = ext + 384;
    const uint32_t sb = (uint32_t)__cvta_generic_to_shared(smraw);

    const int tid = threadIdx.x, lane = tid & 31, wid = tid >> 5;
    const int warp_m = wid >> 2, warp_n = wid & 3;
    const int nb = bx * 128;

    if (tid < 128) bsm[tid] = bias[mb * 128 + tid];
    if (APPLY && tid < 128) {
        m1f[tid] = (float)g_m1[bb * HW + nb + tid];
        m0f[tid] = (float)g_m0[bb * HW + nb + tid];
    }

    const __nv_bfloat16* WH = APPLY ? g_w2h : g_w1h;
    const __nv_bfloat16* WL = APPLY ? g_w2l : g_w1l;
    const __nv_bfloat16* BH = (APPLY ? g_xh : g_fh) + (size_t)bb * HW * 256;
    const __nv_bfloat16* BL = (APPLY ? g_xl : g_fl) + (size_t)bb * HW * 256;

    float acc[4][4][4];
#pragma unroll
    for (int i = 0; i < 4; i++)
#pragma unroll
        for (int j = 0; j < 4; j++)
#pragma unroll
            for (int k = 0; k < 4; k++) acc[i][j][k] = 0.f;

    const int rA = lane >> 2, cA = lane & 3;

    auto issue = [&](int kc, int stage) {
        const int d0 = kc * 32;
        uint32_t base = sb + stage * STAGEW * 4;
#pragma unroll
        for (int it = 0; it < 2; it++) {
            int lin = it * 256 + tid;
            int r = lin >> 2, c = lin & 3;
            uint32_t doff = (r * ROWW + c * 4) * 4;
            size_t aoff = ((size_t)(mb * 128 + r) * 256 + d0 + c * 8);
            size_t boff = ((size_t)(nb + r) * 256 + d0 + c * 8);
            CP16(base + doff, (const char*)WH + aoff * 2);
            CP16(base + MATW * 4 + doff, (const char*)WL + aoff * 2);
            CP16(base + 2 * MATW * 4 + doff, (const char*)BH + boff * 2);
            CP16(base + 3 * MATW * 4 + doff, (const char*)BL + boff * 2);
        }
        CP_COMMIT();
    };

    issue(0, 0);
    issue(1, 1);

#pragma unroll 1
    for (int kc = 0; kc < NCH; kc++) {
        const int stage = kc & 1;
        if (kc < NCH - 1) CP_WAIT1(); else CP_WAIT0();
        __syncthreads();
        const uint32_t* Ah = smw + stage * STAGEW;
        const uint32_t* Al = Ah + MATW;
        const uint32_t* Bh = Al + MATW;
        const uint32_t* Bl2 = Bh + MATW;
#pragma unroll
        for (int kt = 0; kt < 2; kt++) {
            uint32_t Afh[4][4], Afl[4][4];
#pragma unroll
            for (int mt = 0; mt < 4; mt++) {
                int base = (warp_m * 64 + mt * 16 + rA) * ROWW + kt * 8 + cA;
                Afh[mt][0] = Ah[base];
                Afh[mt][1] = Ah[base + 8 * ROWW];
                Afh[mt][2] = Ah[base + 4];
                Afh[mt][3] = Ah[base + 8 * ROWW + 4];
                Afl[mt][0] = Al[base];
                Afl[mt][1] = Al[base + 8 * ROWW];
                Afl[mt][2] = Al[base + 4];
                Afl[mt][3] = Al[base + 8 * ROWW + 4];
            }
#pragma unroll
            for (int nt = 0; nt < 4; nt++) {
                int bbase = (warp_n * 32 + nt * 8 + rA) * ROWW + kt * 8 + cA;
                uint32_t bh0 = Bh[bbase], bh1 = Bh[bbase + 4];
                uint32_t bl0 = Bl2[bbase], bl1 = Bl2[bbase + 4];
#pragma unroll
                for (int mt = 0; mt < 4; mt++) {
                    mma16816(acc[mt][nt], Afh[mt], bh0, bh1);
                    mma16816(acc[mt][nt], Afh[mt], bl0, bl1);
                    mma16816(acc[mt][nt], Afl[mt], bh0, bh1);
                }
            }
        }
        __syncthreads();
        if (kc + 2 < NCH) issue(kc + 2, stage);
    }

    float* outb = (APPLY ? g_proj : g_x) + (size_t)bb * HW * 256;
#pragma unroll
    for (int mt = 0; mt < 4; mt++) {
#pragma unroll
        for (int h = 0; h < 2; h++) {
            int e_local = warp_m * 64 + mt * 16 + rA + h * 8;
            int e = mb * 128 + e_local;
            float bv = bsm[e_local];
            float s0 = 0.f, s1 = 0.f;
#pragma unroll
            for (int nt = 0; nt < 4; nt++) {
                int nc = warp_n * 32 + nt * 8 + cA * 2;
                float v0 = acc[mt][nt][h * 2 + 0] + bv;
                float v1 = acc[mt][nt][h * 2 + 1] + bv;
                outb[(size_t)(nb + nc) * 256 + e] = v0;
                outb[(size_t)(nb + nc + 1) * 256 + e] = v1;
                if (!APPLY) {
                    s0 += v0 + v1;
                    s1 += v0 * v0 + v1 * v1;
                } else {
                    s0 += m1f[nc] * v0 + m1f[nc + 1] * v1;
                    s1 += m0f[nc] * v0 + m0f[nc + 1] * v1;
                }
            }
            s0 += __shfl_down_sync(0xffffffffu, s0, 1, 4);
            s0 += __shfl_down_sync(0xffffffffu, s0, 2, 4);
            s1 += __shfl_down_sync(0xffffffffu, s1, 1, 4);
            s1 += __shfl_down_sync(0xffffffffu, s1, 2, 4);
            if (cA == 0) {
                red[(0 * 128 + e_local) * 4 + warp_n] = s0;
                red[(1 * 128 + e_local) * 4 + warp_n] = s1;
            }
        }
    }
    __syncthreads();
    {
        int q = tid >> 7, e_local = tid & 127;
        int e = mb * 128 + e_local;
        const float* r4 = &red[(q * 128 + e_local) * 4];
        float s = r4[0] + r4[1] + r4[2] + r4[3];
        if (!APPLY) {
            if (q == 0)
                g_ps[(size_t)e * 512 + bb * 128 + bx] = s;
            else
                g_pq[(size_t)e * 512 + bb * 128 + bx] = s;
        } else {
            if (q == 0)
                g_pfg[(size_t)(bb * Dm + e) * NBLK + bx] = s;
            else
                g_pbg[(size_t)(bb * Dm + e) * NBLK + bx] = s;
        }
    }
}

// ---------------- finalize BN stats ------------------------------------------
__global__ __launch_bounds__(128) void k_finstats(const float* __restrict__ gamma,
                                                  const float* __restrict__ beta) {
    __shared__ float shs[4], shq[4];
    int e = blockIdx.x, t = threadIdx.x, lane = t & 31, wp = t >> 5;
    float s = 0.f, q = 0.f;
    for (int i = t; i < 512; i += 128) {
        s += g_ps[e * 512 + i];
        q += g_pq[e * 512 + i];
    }
#pragma unroll
    for (int off = 16; off; off >>= 1) {
        s += __shfl_down_sync(0xffffffffu, s, off);
        q += __shfl_down_sync(0xffffffffu, q, off);
    }
    if (lane == 0) {
        shs[wp] = s;
        shq[wp] = q;
    }
    __syncthreads();
    if (t == 0) {
        float ts = shs[0] + shs[1] + shs[2] + shs[3];
        float tq = shq[0] + shq[1] + shq[2] + shq[3];
        const float inv_n = 1.f / (float)(Bm * HW);
        float mean = ts * inv_n;
        float var = fmaxf(tq * inv_n - mean * mean, 0.f);
        float sc = gamma[e] / sqrtf(var + 1e-5f);
        g_s[e] = sc;
        g_c[e] = beta[e] - mean * sc;
    }
}

// ---------------- finalize prototypes ----------------------------------------
__global__ __launch_bounds__(128) void k_finproto() {
    __shared__ float shf[4], shb[4];
    int e = blockIdx.x, b = blockIdx.y, t = threadIdx.x, lane = t & 31, wp = t >> 5;
    float f = g_pfg[(b * Dm + e) * NBLK + t];
    float g = g_pbg[(b * Dm + e) * NBLK + t];
#pragma unroll
    for (int off = 16; off; off >>= 1) {
        f += __shfl_down_sync(0xffffffffu, f, off);
        g += __shfl_down_sync(0xffffffffu, g, off);
    }
    if (lane == 0) {
        shf[wp] = f;
        shb[wp] = g;
    }
    __syncthreads();
    if (t == 0) {
        g_mfg[b * Dm + e] = shf[0] + shf[1] + shf[2] + shf[3];
        g_mbg[b * Dm + e] = shb[0] + shb[1] + shb[2] + shb[3];
    }
}

// ---------------- dot phase: grid (4 sgroups, 8 tasks) ------------------------
__global__ __launch_bounds__(256) void k_dot() {
    __shared__ float qs[32 * 257];
    __shared__ float vbuf[8][264];
    __shared__ float warpP[8][33];
    int task = blockIdx.y, sg = blockIdx.x;
    int b = task >> 1;
    int tid = threadIdx.x, w = tid >> 5, l = tid & 31;
    const float* projb = g_proj + (size_t)b * HW * 256;

    for (int q = 0; q < 4; q++) {
        int a = w * 4 + q;
        const float* src = projb + (size_t)g_aidx[task * 32 + a] * 256;
        float v[8], ss = 0.f;
#pragma unroll
        for (int cc = 0; cc < 8; cc++) {
            v[cc] = src[l + 32 * cc];
            ss = fmaf(v[cc], v[cc], ss);
        }
#pragma unroll
        for (int off = 16; off; off >>= 1) ss += __shfl_xor_sync(0xffffffffu, ss, off);
        float sc = 1.f / fmaxf(sqrtf(ss), 1e-12f);
#pragma unroll
        for (int cc = 0; cc < 8; cc++) qs[a * 257 + l + 32 * cc] = v[cc] * sc;
    }
    __syncthreads();

    float accv = 0.f;
    for (int q = 0; q < 4; q++) {
        int s = sg * 32 + w + q * 8;
        bool isP = s < 64;
        int si = isP ? s : s - 64;
        float fl = isP ? g_pflag[task * 64 + si] : g_nflag[task * 64 + si];
        if (fl != 0.f) {
            int idx = isP ? g_pidx[task * 64 + si] : g_nidx[task * 64 + si];
            const float* src = projb + (size_t)idx * 256;
            float v[8], ss = 0.f;
#pragma unroll
            for (int cc = 0; cc < 8; cc++) {
                v[cc] = src[l + 32 * cc];
                ss = fmaf(v[cc], v[cc], ss);
            }
#pragma unroll
            for (int off = 16; off; off >>= 1) ss += __shfl_xor_sync(0xffffffffu, ss, off);
            float sc = 1.f / fmaxf(sqrtf(ss), 1e-12f);
#pragma unroll
            for (int cc = 0; cc < 8; cc++) vbuf[w][l + 32 * cc] = v[cc] * sc;
            __syncwarp();
            float dot = 0.f;
            const float* qrow = &qs[l * 257];
#pragma unroll 8
            for (int d = 0; d < 256; d++) dot = fmaf(qrow[d], vbuf[w][d], dot);
            accv += expf(dot * 10.f);
            __syncwarp();
        }
    }
    warpP[w][l] = accv;
    __syncthreads();
    if (w == 0) {
        float p = 0.f;
#pragma unroll
        for (int ww = 0; ww < 8; ww++) p += warpP[ww][l];
        g_dacc[(task * 4 + sg) * 32 + l] = p;
    }
}

// ---------------- final: pair finalize + local + global loss -----------------
__global__ __launch_bounds__(256) void k_final(float* __restrict__ out, int out_size) {
    __shared__ float scratch[34];
    __shared__ float qf[4][257], qb[4][257];
    __shared__ float cf[4], cb[4];
    __shared__ float pfv[4], pbv[4], nfv[4], nbv[4];
    __shared__ float sbl[8];
    __shared__ int sinc[8];
    int tid = threadIdx.x;

    // pair finalize: warp = task, lane = anchor
    {
        int task = tid >> 5, l = tid & 31;
        float p = g_dacc[(task * 4 + 0) * 32 + l] + g_dacc[(task * 4 + 1) * 32 + l];
        float n = g_dacc[(task * 4 + 2) * 32 + l] + g_dacc[(task * 4 + 3) * 32 + l];
        bool inc = (g_cA[task] >= 1) && (g_cB[task] >= 1);
        if (!inc) p += 1.f;
        float per = -logf(p / (p + n + 1e-8f));
        float af = g_aflag[task * 32 + l];
        float ws = per * af, as = af;
#pragma unroll
        for (int off = 16; off; off >>= 1) {
            ws += __shfl_down_sync(0xffffffffu, ws, off);
            as += __shfl_down_sync(0xffffffffu, as, off);
        }
        if (l == 0) {
            sbl[task] = inc ? (ws / fmaxf(as, 1.f)) : 0.f;
            sinc[task] = inc ? 1 : 0;
        }
    }
    __syncthreads();

    for (int b = 0; b < 4; b++) {
        float c1 = 0.f, c0 = 0.f;
        for (int i = tid; i < HW; i += 256) {
            c1 += (float)g_m1[b * HW + i];
            c0 += (float)g_m0[b * HW + i];
        }
        float s1 = blk_sum(scratch, c1, tid);
        float s0 = blk_sum(scratch, c0, tid);
        if (tid == 0) { cf[b] = s1; cb[b] = s0; }
    }
    __syncthreads();

    for (int b = 0; b < 4; b++) {
        float mf = g_mfg[b * Dm + tid] / fmaxf(cf[b], 1.f);
        float mb_ = g_mbg[b * Dm + tid] / fmaxf(cb[b], 1.f);
        float ssf = blk_sum(scratch, mf * mf, tid);
        qf[b][tid] = mf / fmaxf(sqrtf(ssf), 1e-12f);
        float ssb = blk_sum(scratch, mb_ * mb_, tid);
        qb[b][tid] = mb_ / fmaxf(sqrtf(ssb), 1e-12f);
    }
    __syncthreads();

    for (int b = 0; b < 4; b++) {
        float d1 = blk_sum(scratch, qf[b][tid] * qf[b][tid], tid);
        float d2 = blk_sum(scratch, qb[b][tid] * qb[b][tid], tid);
        if (tid == 0) {
            pfv[b] = expf(d1 * 10.f);
            pbv[b] = expf(d2 * 10.f);
            nfv[b] = 0.f;
            nbv[b] = 0.f;
        }
        __syncthreads();
    }
    for (int b = 0; b < 4; b++) {
        for (int j = 0; j <= b; j++) {
            float dqbqf = blk_sum(scratch, qb[j][tid] * qf[b][tid], tid);
            float dqfqb = blk_sum(scratch, qf[j][tid] * qb[b][tid], tid);
            if (tid == 0) {
                bool vgj = (cf[j] >= 1.f) && (cb[j] >= 1.f);
                if (vgj) {
                    nfv[b] += expf(dqbqf * 10.f);
                    nbv[b] += expf(dqfqb * 10.f);
                }
            }
            __syncthreads();
        }
    }

    if (tid == 0) {
        float lsum = 0.f;
        int icnt = 0;
        for (int t = 0; t < 8; t++) {
            lsum += sbl[t];
            icnt += sinc[t];
        }
        float l_local = lsum / (float)max(icnt, 1);
        float gs = 0.f;
        int vcnt = 0;
        for (int b = 0; b < 4; b++) {
            bool vg = (cf[b] >= 1.f) && (cb[b] >= 1.f);
            if (vg) {
                float lg = -logf(pfv[b] / (pfv[b] + nfv[b] + 1e-8f)) -
                           logf(pbv[b] / (pbv[b] + nbv[b] + 1e-8f));
                gs += lg;
                vcnt++;
            }
        }
        float l_global = gs / (float)max(vcnt, 1);
        if (out_size > 0) out[0] = l_local + 0.5f * l_global;
        if (out_size > 1) out[1] = l_local;
        if (out_size > 2) out[2] = l_global;
    }
}

// ---------------- launch ------------------------------------------------------
extern "C" void kernel_launch(void* const* d_in, const int* in_sizes, int n_in, void* d_out,
                              int out_size) {
    const float* feat = (const float*)d_in[0];
    const int* labels = (const int*)d_in[1];
    const float* prob_ori = (const float*)d_in[2];
    const float* prob_aug = (const float*)d_in[3];
    const float* unc = (const float*)d_in[4];
    const float* r_anc = (const float*)d_in[5];
    const float* r_pos = (const float*)d_in[6];
    const float* r_neg = (const float*)d_in[7];
    const float* w1 = (const float*)d_in[8];
    const float* b1 = (const float*)d_in[9];
    const float* gamma = (const float*)d_in[10];
    const float* beta = (const float*)d_in[11];
    const float* w2 = (const float*)d_in[12];
    const float* b2 = (const float*)d_in[13];

    cudaFuncSetAttribute(k_gemm_mma<false>, cudaFuncAttributeMaxDynamicSharedMemorySize,
                         GEMM_SMEM);
    cudaFuncSetAttribute(k_gemm_mma<true>, cudaFuncAttributeMaxDynamicSharedMemorySize,
                         GEMM_SMEM);

    k_masks<<<(Bm * HW + 255) / 256, 256>>>(prob_ori, prob_aug, unc, labels);
    k_splitw<<<dim3(Dm * Dm / 2 / 256, 2), 256>>>(w1, w2);
    k_split_feat<<<dim3(HW / 64, Dm / 64, Bm), 256>>>(feat);
    // GEMM1 fused with selection: blocks 0-7 select, 8..1031 GEMM
    k_gemm_mma<false><<<8 + NBLK * 2 * Bm, 256, GEMM_SMEM>>>(b1, unc, r_anc, r_pos, r_neg);
    k_finstats<<<Dm, 128>>>(gamma, beta);
    k_bnsplit<<<Bm * HW / 8, 256>>>();
    k_gemm_mma<true><<<NBLK * 2 * Bm, 256, GEMM_SMEM>>>(b2, nullptr, nullptr, nullptr, nullptr);
    k_finproto<<<dim3(Dm, Bm), 128>>>();
    k_dot<<<dim3(4, 8), 256>>>();
    k_final<<<1, 256>>>((float*)d_out, out_size);
}

// round 10
// speedup vs baseline: 1.4269x; 1.0008x over previous
#include <cuda_runtime.h>
#include <cuda_bf16.h>
#include <float.h>
#include <math.h>
#include <stdint.h>

#define HW 16384
#define Dm 256
#define Bm 4
#define NBLK 128

// ---------------- scratch ----------------------------------------------------
__device__ float g_x[Bm * HW * Dm];
__device__ float g_proj[Bm * HW * Dm];
__device__ __nv_bfloat16 g_fh[Bm * HW * Dm];
__device__ __nv_bfloat16 g_fl[Bm * HW * Dm];
__device__ __nv_bfloat16 g_xh[Bm * HW * Dm];
__device__ __nv_bfloat16 g_xl[Bm * HW * Dm];
__device__ __nv_bfloat16 g_w1h[Dm * Dm], g_w1l[Dm * Dm];
__device__ __nv_bfloat16 g_w2h[Dm * Dm], g_w2l[Dm * Dm];
__device__ float g_s[Dm];
__device__ float g_c[Dm];
__device__ unsigned char g_m1[Bm * HW];
__device__ unsigned char g_m0[Bm * HW];
__device__ float g_ps[Dm * 512];
__device__ float g_pq[Dm * 512];
__device__ float g_pfg[Bm * Dm * NBLK];
__device__ float g_pbg[Bm * Dm * NBLK];
__device__ float g_mfg[Bm * Dm];
__device__ float g_mbg[Bm * Dm];
// selection outputs
__device__ int g_aidx[8 * 32];
__device__ float g_aflag[8 * 32];
__device__ int g_pidx[8 * 64];
__device__ float g_pflag[8 * 64];
__device__ int g_nidx[8 * 64];
__device__ float g_nflag[8 * 64];
__device__ int g_cA[8], g_cB[8];
__device__ float g_dacc[8 * 4 * 32];

// ---------------- block reduction --------------------------------------------
__device__ __forceinline__ float blk_sum(volatile float* scratch, float v, int tid) {
    int lane = tid & 31, w = tid >> 5;
#pragma unroll
    for (int off = 16; off; off >>= 1) v += __shfl_down_sync(0xffffffffu, v, off);
    if (lane == 0) scratch[w] = v;
    __syncthreads();
    if (w == 0) {
        v = (lane < 8) ? scratch[lane] : 0.f;
#pragma unroll
        for (int off = 4; off; off >>= 1) v += __shfl_down_sync(0xffffffffu, v, off);
        if (lane == 0) scratch[32] = v;
    }
    __syncthreads();
    return scratch[32];
}

// ---------------- masks ------------------------------------------------------
__global__ void k_masks(const float* __restrict__ prob_ori, const float* __restrict__ prob_aug,
                        const float* __restrict__ unc, const int* __restrict__ labels) {
    int idx = blockIdx.x * blockDim.x + threadIdx.x;
    if (idx >= Bm * HW) return;
    int b = idx >> 14;
    int hw = idx & (HW - 1);
    const float* po = prob_ori + (size_t)b * 2 * HW;
    const float* pa = prob_aug + (size_t)b * 2 * HW;
    int io = po[HW + hw] > po[hw];
    int ia = pa[HW + hw] > pa[hw];
    bool rel = (io == ia);
    bool diff = unc[idx] > 0.5f;
    int lab = labels[idx];
    bool valid = rel && diff;
    g_m1[idx] = (unsigned char)(valid && lab == 1);
    g_m0[idx] = (unsigned char)(valid && lab == 0);
}

// ---------------- bf16 hi/lo split -------------------------------------------
__device__ __forceinline__ void split2(float a, float b, uint32_t& h, uint32_t& l) {
    __nv_bfloat16 ah = __float2bfloat16_rn(a), bh = __float2bfloat16_rn(b);
    float ar = a - __bfloat162float(ah), br = b - __bfloat162float(bh);
    __nv_bfloat16 al = __float2bfloat16_rn(ar), bl = __float2bfloat16_rn(br);
    h = (uint32_t)*(unsigned short*)&ah | ((uint32_t)*(unsigned short*)&bh << 16);
    l = (uint32_t)*(unsigned short*)&al | ((uint32_t)*(unsigned short*)&bl << 16);
}

__device__ __forceinline__ void mma16816(float* c, const uint32_t* a, uint32_t b0, uint32_t b1) {
    asm volatile(
        "mma.sync.aligned.m16n8k16.row.col.f32.bf16.bf16.f32 "
        "{%0,%1,%2,%3}, {%4,%5,%6,%7}, {%8,%9}, {%0,%1,%2,%3};"
        : "+f"(c[0]), "+f"(c[1]), "+f"(c[2]), "+f"(c[3])
        : "r"(a[0]), "r"(a[1]), "r"(a[2]), "r"(a[3]), "r"(b0), "r"(b1));
}

__device__ __forceinline__ void ldsm_x4(uint32_t* r, uint32_t addr) {
    asm volatile("ldmatrix.sync.aligned.m8n8.x4.shared.b16 {%0,%1,%2,%3}, [%4];"
                 : "=r"(r[0]), "=r"(r[1]), "=r"(r[2]), "=r"(r[3])
                 : "r"(addr));
}
__device__ __forceinline__ void ldsm_x2(uint32_t& r0, uint32_t& r1, uint32_t addr) {
    asm volatile("ldmatrix.sync.aligned.m8n8.x2.shared.b16 {%0,%1}, [%2];"
                 : "=r"(r0), "=r"(r1)
                 : "r"(addr));
}

#define CP16(dst_u32, src_ptr) \
    asm volatile("cp.async.cg.shared.global [%0], [%1], 16;" ::"r"(dst_u32), "l"(src_ptr))
#define CP_COMMIT() asm volatile("cp.async.commit_group;" ::: "memory")
#define CP_WAIT1() asm volatile("cp.async.wait_group 1;" ::: "memory")
#define CP_WAIT0() asm volatile("cp.async.wait_group 0;" ::: "memory")

// ---------------- split weights ----------------------------------------------
__global__ __launch_bounds__(256) void k_splitw(const float* __restrict__ w1,
                                                const float* __restrict__ w2) {
    int sel = blockIdx.y;
    const float* w = sel ? w2 : w1;
    uint32_t* oh = (uint32_t*)(sel ? g_w2h : g_w1h);
    uint32_t* ol = (uint32_t*)(sel ? g_w2l : g_w1l);
    int p = blockIdx.x * 256 + threadIdx.x;
    if (p < Dm * Dm / 2) {
        float a = w[2 * p], b = w[2 * p + 1];
        uint32_t h, l;
        split2(a, b, h, l);
        oh[p] = h;
        ol[p] = l;
    }
}

// ---------------- split+transpose feat ---------------------------------------
__global__ __launch_bounds__(256) void k_split_feat(const float* __restrict__ feat) {
    __shared__ float tile[64 * 65];
    int b = blockIdx.z, d0 = blockIdx.y * 64, n0 = blockIdx.x * 64;
    const float* src = feat + ((size_t)b * Dm + d0) * HW + n0;
    int tid = threadIdx.x;
#pragma unroll
    for (int it = 0; it < 4; it++) {
        int lin = it * 256 + tid;
        int r = lin >> 4, c4 = lin & 15;
        float4 v = *(const float4*)(src + (size_t)r * HW + c4 * 4);
        tile[r * 65 + c4 * 4 + 0] = v.x;
        tile[r * 65 + c4 * 4 + 1] = v.y;
        tile[r * 65 + c4 * 4 + 2] = v.z;
        tile[r * 65 + c4 * 4 + 3] = v.w;
    }
    __syncthreads();
    uint32_t* oh = (uint32_t*)g_fh;
    uint32_t* ol = (uint32_t*)g_fl;
#pragma unroll
    for (int it = 0; it < 8; it++) {
        int lin = it * 256 + tid;
        int n = lin >> 5, c = lin & 31;
        float v0 = tile[(2 * c) * 65 + n];
        float v1 = tile[(2 * c + 1) * 65 + n];
        uint32_t h, l;
        split2(v0, v1, h, l);
        size_t o = (((size_t)b * HW + n0 + n) * 256 + d0) / 2 + c;
        oh[o] = h;
        ol[o] = l;
    }
}

// ---------------- bn+relu+split ----------------------------------------------
__global__ __launch_bounds__(256) void k_bnsplit() {
    __shared__ float scs[256], scc[256];
    int tid = threadIdx.x;
    scs[tid] = g_s[tid];
    scc[tid] = g_c[tid];
    __syncthreads();
    size_t row = (size_t)blockIdx.x * 8 + (tid >> 5);
    int d0 = (tid & 31) * 8;
    const float* src = g_x + row * 256 + d0;
    float4 a = *(const float4*)src, b4 = *(const float4*)(src + 4);
    float v[8] = {a.x, a.y, a.z, a.w, b4.x, b4.y, b4.z, b4.w};
#pragma unroll
    for (int j = 0; j < 8; j++) v[j] = fmaxf(fmaf(scs[d0 + j], v[j], scc[d0 + j]), 0.f);
    uint32_t H[4], L[4];
#pragma unroll
    for (int j = 0; j < 4; j++) split2(v[2 * j], v[2 * j + 1], H[j], L[j]);
    size_t o = row * 128 + d0 / 2;
    *(uint4*)&((uint32_t*)g_xh)[o] = make_uint4(H[0], H[1], H[2], H[3]);
    *(uint4*)&((uint32_t*)g_xl)[o] = make_uint4(L[0], L[1], L[2], L[3]);
}

// ---------------- selection (smem struct + helpers) ---------------------------
struct PairS {
    unsigned short listA[HW];
    unsigned short listN[HW];
    unsigned long long sbuf[512];
    int hist[256];
    float red[34];
    int redi[34];
    int cidx[128];
    float cflag[128];
    int cntA, cntN, coll, bstar;
    float bestv;
    int besti;
};

__device__ __forceinline__ void pair_argmax(PairS* S, float v, int i, int tid) {
    int lane = tid & 31, w = tid >> 5;
#pragma unroll
    for (int off = 16; off; off >>= 1) {
        float ov = __shfl_down_sync(0xffffffffu, v, off);
        int oi = __shfl_down_sync(0xffffffffu, i, off);
        if (ov > v || (ov == v && oi < i)) { v = ov; i = oi; }
    }
    if (lane == 0) { S->red[w] = v; S->redi[w] = i; }
    __syncthreads();
    if (w == 0) {
        v = (lane < 8) ? S->red[lane] : -FLT_MAX;
        i = (lane < 8) ? S->redi[lane] : 0x7FFFFFFF;
#pragma unroll
        for (int off = 4; off; off >>= 1) {
            float ov = __shfl_down_sync(0xffffffffu, v, off);
            int oi = __shfl_down_sync(0xffffffffu, i, off);
            if (ov > v || (ov == v && oi < i)) { v = ov; i = oi; }
        }
        if (lane == 0) { S->bestv = v; S->besti = i; }
    }
    __syncthreads();
}

__device__ void select_topk(PairS* S, const unsigned short* list, int cnt,
                            const float* __restrict__ key, int K, int* oidx, float* oflag,
                            int tid) {
    float lastv = FLT_MAX;
    int lasti = -1;
    for (int kk = 0; kk < K; kk++) {
        float bv = -FLT_MAX;
        int bi = 0x7FFFFFFF;
        for (int ii = tid; ii < cnt; ii += 256) {
            int idx = list[ii];
            float v = key[idx];
            if (v < lastv || (v == lastv && idx > lasti)) {
                if (v > bv || (v == bv && idx < bi)) { bv = v; bi = idx; }
            }
        }
        pair_argmax(S, bv, bi, tid);
        float gbv = S->bestv;
        int gbi = S->besti;
        if (gbv > -FLT_MAX) {
            lastv = gbv;
            lasti = gbi;
            if (tid == 0) { oidx[kk] = gbi; oflag[kk] = 1.f; }
        } else {
            lastv = -FLT_MAX;
            lasti = 0x7FFFFFFF;
            if (tid == 0) { oidx[kk] = 0; oflag[kk] = 0.f; }
        }
        __syncthreads();
    }
}

__device__ void bitonic_desc(PairS* S, int n, int tid) {
    for (int k = 2; k <= n; k <<= 1)
        for (int j = k >> 1; j > 0; j >>= 1) {
            for (int t = tid; t < n; t += 256) {
                int ixj = t ^ j;
                if (ixj > t) {
                    unsigned long long x = S->sbuf[t], y = S->sbuf[ixj];
                    bool desc = ((t & k) == 0);
                    if (desc ? (x < y) : (x > y)) {
                        S->sbuf[t] = y;
                        S->sbuf[ixj] = x;
                    }
                }
            }
            __syncthreads();
        }
}

__device__ void radix_select(PairS* S, const unsigned short* list, int cnt,
                             const float* __restrict__ key, int K, int* oidx, float* oflag,
                             int tid) {
    int target = min(K, cnt);
    if (target == 0) {
        for (int kk = tid; kk < K; kk += 256) { oidx[kk] = 0; oflag[kk] = 0.f; }
        __syncthreads();
        return;
    }
    S->hist[tid] = 0;
    __syncthreads();
    for (int ii = tid; ii < cnt; ii += 256) {
        float r = key[list[ii]];
        int b = (int)(r * 256.f);
        b = b < 0 ? 0 : (b > 255 ? 255 : b);
        atomicAdd(&S->hist[b], 1);
    }
    __syncthreads();
    if (tid == 0) {
        int acc = 0, bs = 0;
        for (int b = 255; b >= 0; b--) {
            acc += S->hist[b];
            if (acc >= target) { bs = b; break; }
        }
        S->bstar = bs;
        S->coll = 0;
    }
    __syncthreads();
    int bstar = S->bstar;
    for (int ii = tid; ii < cnt; ii += 256) {
        int idx = list[ii];
        float r = key[idx];
        int b = (int)(r * 256.f);
        b = b < 0 ? 0 : (b > 255 ? 255 : b);
        if (b >= bstar) {
            int p = atomicAdd(&S->coll, 1);
            if (p < 512)
                S->sbuf[p] = ((unsigned long long)__float_as_uint(r) << 32) |
                             (unsigned long long)(unsigned int)(~(unsigned int)idx);
        }
    }
    __syncthreads();
    int coll = S->coll;
    if (coll > 512) {
        select_topk(S, list, cnt, key, K, oidx, oflag, tid);
        return;
    }
    int n = 1;
    while (n < coll) n <<= 1;
    for (int i = coll + tid; i < n; i += 256) S->sbuf[i] = 0ull;
    __syncthreads();
    bitonic_desc(S, n, tid);
    for (int kk = tid; kk < K; kk += 256) {
        if (kk < target) {
            oidx[kk] = (int)(~(unsigned int)(S->sbuf[kk] & 0xFFFFFFFFull));
            oflag[kk] = 1.f;
        } else {
            oidx[kk] = 0;
            oflag[kk] = 0.f;
        }
    }
    __syncthreads();
}

__device__ void hard_select(PairS* S, const float* __restrict__ ub, int* oidx, float* oflag,
                            int tid) {
    if (tid < 128) {
        unsigned long long kv;
        if (S->cflag[tid] != 0.f) {
            unsigned int u = __float_as_uint(ub[S->cidx[tid]]) + 1u;
            kv = ((unsigned long long)u << 32) |
                 (unsigned long long)(unsigned int)(~(unsigned int)tid);
        } else {
            kv = (unsigned long long)(unsigned int)(~(unsigned int)tid);
        }
        S->sbuf[tid] = kv;
    }
    __syncthreads();
    bitonic_desc(S, 128, tid);
    if (tid < 64) {
        int t = (int)((~(unsigned int)(S->sbuf[tid] & 0xFFFFFFFFull)) & 127u);
        oidx[tid] = S->cidx[t];
        oflag[tid] = S->cflag[t];
    }
    __syncthreads();
}

__device__ void do_select(char* smraw, int task, const float* unc, const float* r_anc,
                          const float* r_pos, const float* r_neg) {
    PairS* S = (PairS*)smraw;
    int b = task >> 1, c = task & 1;
    int tid = threadIdx.x;
    const unsigned char* am = (c == 0 ? g_m1 : g_m0) + b * HW;
    const unsigned char* nm = (c == 0 ? g_m0 : g_m1) + b * HW;

    if (tid == 0) { S->cntA = 0; S->cntN = 0; }
    __syncthreads();
    for (int i = tid; i < HW; i += 256) {
        if (am[i]) { int p = atomicAdd(&S->cntA, 1); S->listA[p] = (unsigned short)i; }
        if (nm[i]) { int p = atomicAdd(&S->cntN, 1); S->listN[p] = (unsigned short)i; }
    }
    __syncthreads();
    int cntA = S->cntA, cntN = S->cntN;

    const float* ra = r_anc + ((size_t)b * 2 + c) * HW;
    const float* rp = r_pos + ((size_t)b * 2 + c) * HW;
    const float* rn = r_neg + ((size_t)b * 2 + c) * HW;
    const float* ub = unc + (size_t)b * HW;

    radix_select(S, S->listA, cntA, ra, 32, g_aidx + task * 32, g_aflag + task * 32, tid);
    radix_select(S, S->listA, cntA, rp, 128, S->cidx, S->cflag, tid);
    hard_select(S, ub, g_pidx + task * 64, g_pflag + task * 64, tid);
    radix_select(S, S->listN, cntN, rn, 128, S->cidx, S->cflag, tid);
    hard_select(S, ub, g_nidx + task * 64, g_nflag + task * 64, tid);

    if (tid == 0) {
        g_cA[task] = cntA;
        g_cB[task] = cntN;
    }
}

// ---------------- pure-bf16 HMMA GEMM ----------------------------------------
#define ROWW 20
#define MATW (128 * ROWW)
#define STAGEW (4 * MATW)
#define OFF_EXT (2 * STAGEW)
#define GEMM_SMEM ((OFF_EXT + 1408) * 4)  // 87552 bytes
#define NCH 8

template <bool APPLY>
__global__ __launch_bounds__(256, 2) void k_gemm_mma(const float* __restrict__ bias,
                                                     const float* __restrict__ unc,
                                                     const float* __restrict__ r_anc,
                                                     const float* __restrict__ r_pos,
                                                     const float* __restrict__ r_neg) {
    extern __shared__ __align__(16) char smraw[];
    int Bl = blockIdx.x;
    if (!APPLY) {
        if (Bl < 8) {
            do_select(smraw, Bl, unc, r_anc, r_pos, r_neg);
            return;
        }
        Bl -= 8;
    }
    const int bx = Bl & 127, mb = (Bl >> 7) & 1, bb = Bl >> 8;

    float* ext = (float*)smraw + OFF_EXT;
    float* bsm = ext;
    float* m1f = ext + 128;
    float* m0f = ext + 256;
    float* red = ext + 384;
    const uint32_t sb = (uint32_t)__cvta_generic_to_shared(smraw);

    const int tid = threadIdx.x, lane = tid & 31, wid = tid >> 5;
    const int warp_m = wid >> 2, warp_n = wid & 3;
    const int nb = bx * 128;

    if (tid < 128) bsm[tid] = bias[mb * 128 + tid];
    if (APPLY && tid < 128) {
        m1f[tid] = (float)g_m1[bb * HW + nb + tid];
        m0f[tid] = (float)g_m0[bb * HW + nb + tid];
    }

    const __nv_bfloat16* WH = APPLY ? g_w2h : g_w1h;
    const __nv_bfloat16* WL = APPLY ? g_w2l : g_w1l;
    const __nv_bfloat16* BH = (APPLY ? g_xh : g_fh) + (size_t)bb * HW * 256;
    const __nv_bfloat16* BL = (APPLY ? g_xl : g_fl) + (size_t)bb * HW * 256;

    float acc[4][4][4];
#pragma unroll
    for (int i = 0; i < 4; i++)
#pragma unroll
        for (int j = 0; j < 4; j++)
#pragma unroll
            for (int k = 0; k < 4; k++) acc[i][j][k] = 0.f;

    const int rA = lane >> 2, cA = lane & 3;
    // ldmatrix per-lane byte offsets within a tile
    const int aLane = (warp_m * 64 + (lane & 15)) * 80 + (lane >> 4) * 16;
    const int bLane = (warp_n * 32 + (lane & 7)) * 80 + ((lane >> 3) & 1) * 16;

    auto issue = [&](int kc, int stage) {
        const int d0 = kc * 32;
        uint32_t base = sb + stage * STAGEW * 4;
#pragma unroll
        for (int it = 0; it < 2; it++) {
            int lin = it * 256 + tid;
            int r = lin >> 2, c = lin & 3;
            uint32_t doff = (r * ROWW + c * 4) * 4;
            size_t aoff = ((size_t)(mb * 128 + r) * 256 + d0 + c * 8);
            size_t boff = ((size_t)(nb + r) * 256 + d0 + c * 8);
            CP16(base + doff, (const char*)WH + aoff * 2);
            CP16(base + MATW * 4 + doff, (const char*)WL + aoff * 2);
            CP16(base + 2 * MATW * 4 + doff, (const char*)BH + boff * 2);
            CP16(base + 3 * MATW * 4 + doff, (const char*)BL + boff * 2);
        }
        CP_COMMIT();
    };

    issue(0, 0);
    issue(1, 1);

#pragma unroll 1
    for (int kc = 0; kc < NCH; kc++) {
        const int stage = kc & 1;
        if (kc < NCH - 1) CP_WAIT1(); else CP_WAIT0();
        __syncthreads();
        uint32_t AhB = sb + stage * STAGEW * 4;
        uint32_t AlB = AhB + MATW * 4;
        uint32_t BhB = AlB + MATW * 4;
        uint32_t BlB = BhB + MATW * 4;
#pragma unroll
        for (int kt = 0; kt < 2; kt++) {
            uint32_t Afh[4][4], Afl[4][4];
#pragma unroll
            for (int mt = 0; mt < 4; mt++) {
                ldsm_x4(Afh[mt], AhB + aLane + mt * 16 * 80 + kt * 32);
                ldsm_x4(Afl[mt], AlB + aLane + mt * 16 * 80 + kt * 32);
            }
#pragma unroll
            for (int nt = 0; nt < 4; nt++) {
                uint32_t bh0, bh1, bl0, bl1;
                ldsm_x2(bh0, bh1, BhB + bLane + nt * 8 * 80 + kt * 32);
                ldsm_x2(bl0, bl1, BlB + bLane + nt * 8 * 80 + kt * 32);
#pragma unroll
                for (int mt = 0; mt < 4; mt++) {
                    mma16816(acc[mt][nt], Afh[mt], bh0, bh1);
                    mma16816(acc[mt][nt], Afh[mt], bl0, bl1);
                    mma16816(acc[mt][nt], Afl[mt], bh0, bh1);
                }
            }
        }
        __syncthreads();
        if (kc + 2 < NCH) issue(kc + 2, stage);
    }

    float* outb = (APPLY ? g_proj : g_x) + (size_t)bb * HW * 256;
#pragma unroll
    for (int mt = 0; mt < 4; mt++) {
#pragma unroll
        for (int h = 0; h < 2; h++) {
            int e_local = warp_m * 64 + mt * 16 + rA + h * 8;
            int e = mb * 128 + e_local;
            float bv = bsm[e_local];
            float s0 = 0.f, s1 = 0.f;
#pragma unroll
            for (int nt = 0; nt < 4; nt++) {
                int nc = warp_n * 32 + nt * 8 + cA * 2;
                float v0 = acc[mt][nt][h * 2 + 0] + bv;
                float v1 = acc[mt][nt][h * 2 + 1] + bv;
                outb[(size_t)(nb + nc) * 256 + e] = v0;
                outb[(size_t)(nb + nc + 1) * 256 + e] = v1;
                if (!APPLY) {
                    s0 += v0 + v1;
                    s1 += v0 * v0 + v1 * v1;
                } else {
                    s0 += m1f[nc] * v0 + m1f[nc + 1] * v1;
                    s1 += m0f[nc] * v0 + m0f[nc + 1] * v1;
                }
            }
            s0 += __shfl_down_sync(0xffffffffu, s0, 1, 4);
            s0 += __shfl_down_sync(0xffffffffu, s0, 2, 4);
            s1 += __shfl_down_sync(0xffffffffu, s1, 1, 4);
            s1 += __shfl_down_sync(0xffffffffu, s1, 2, 4);
            if (cA == 0) {
                red[(0 * 128 + e_local) * 4 + warp_n] = s0;
                red[(1 * 128 + e_local) * 4 + warp_n] = s1;
            }
        }
    }
    __syncthreads();
    {
        int q = tid >> 7, e_local = tid & 127;
        int e = mb * 128 + e_local;
        const float* r4 = &red[(q * 128 + e_local) * 4];
        float s = r4[0] + r4[1] + r4[2] + r4[3];
        if (!APPLY) {
            if (q == 0)
                g_ps[(size_t)e * 512 + bb * 128 + bx] = s;
            else
                g_pq[(size_t)e * 512 + bb * 128 + bx] = s;
        } else {
            if (q == 0)
                g_pfg[(size_t)(bb * Dm + e) * NBLK + bx] = s;
            else
                g_pbg[(size_t)(bb * Dm + e) * NBLK + bx] = s;
        }
    }
}

// ---------------- finalize BN stats ------------------------------------------
__global__ __launch_bounds__(128) void k_finstats(const float* __restrict__ gamma,
                                                  const float* __restrict__ beta) {
    __shared__ float shs[4], shq[4];
    int e = blockIdx.x, t = threadIdx.x, lane = t & 31, wp = t >> 5;
    float s = 0.f, q = 0.f;
    for (int i = t; i < 512; i += 128) {
        s += g_ps[e * 512 + i];
        q += g_pq[e * 512 + i];
    }
#pragma unroll
    for (int off = 16; off; off >>= 1) {
        s += __shfl_down_sync(0xffffffffu, s, off);
        q += __shfl_down_sync(0xffffffffu, q, off);
    }
    if (lane == 0) {
        shs[wp] = s;
        shq[wp] = q;
    }
    __syncthreads();
    if (t == 0) {
        float ts = shs[0] + shs[1] + shs[2] + shs[3];
        float tq = shq[0] + shq[1] + shq[2] + shq[3];
        const float inv_n = 1.f / (float)(Bm * HW);
        float mean = ts * inv_n;
        float var = fmaxf(tq * inv_n - mean * mean, 0.f);
        float sc = gamma[e] / sqrtf(var + 1e-5f);
        g_s[e] = sc;
        g_c[e] = beta[e] - mean * sc;
    }
}

// ---------------- finalize prototypes ----------------------------------------
__global__ __launch_bounds__(128) void k_finproto() {
    __shared__ float shf[4], shb[4];
    int e = blockIdx.x, b = blockIdx.y, t = threadIdx.x, lane = t & 31, wp = t >> 5;
    float f = g_pfg[(b * Dm + e) * NBLK + t];
    float g = g_pbg[(b * Dm + e) * NBLK + t];
#pragma unroll
    for (int off = 16; off; off >>= 1) {
        f += __shfl_down_sync(0xffffffffu, f, off);
        g += __shfl_down_sync(0xffffffffu, g, off);
    }
    if (lane == 0) {
        shf[wp] = f;
        shb[wp] = g;
    }
    __syncthreads();
    if (t == 0) {
        g_mfg[b * Dm + e] = shf[0] + shf[1] + shf[2] + shf[3];
        g_mbg[b * Dm + e] = shb[0] + shb[1] + shb[2] + shb[3];
    }
}

// ---------------- dot phase: grid (4 sgroups, 8 tasks) ------------------------
__global__ __launch_bounds__(256) void k_dot() {
    __shared__ float qs[32 * 257];
    __shared__ float vbuf[8][264];
    __shared__ float warpP[8][33];
    int task = blockIdx.y, sg = blockIdx.x;
    int b = task >> 1;
    int tid = threadIdx.x, w = tid >> 5, l = tid & 31;
    const float* projb = g_proj + (size_t)b * HW * 256;

    for (int q = 0; q < 4; q++) {
        int a = w * 4 + q;
        const float* src = projb + (size_t)g_aidx[task * 32 + a] * 256;
        float v[8], ss = 0.f;
#pragma unroll
        for (int cc = 0; cc < 8; cc++) {
            v[cc] = src[l + 32 * cc];
            ss = fmaf(v[cc], v[cc], ss);
        }
#pragma unroll
        for (int off = 16; off; off >>= 1) ss += __shfl_xor_sync(0xffffffffu, ss, off);
        float sc = 1.f / fmaxf(sqrtf(ss), 1e-12f);
#pragma unroll
        for (int cc = 0; cc < 8; cc++) qs[a * 257 + l + 32 * cc] = v[cc] * sc;
    }
    __syncthreads();

    float accv = 0.f;
    for (int q = 0; q < 4; q++) {
        int s = sg * 32 + w + q * 8;
        bool isP = s < 64;
        int si = isP ? s : s - 64;
        float fl = isP ? g_pflag[task * 64 + si] : g_nflag[task * 64 + si];
        if (fl != 0.f) {
            int idx = isP ? g_pidx[task * 64 + si] : g_nidx[task * 64 + si];
            const float* src = projb + (size_t)idx * 256;
            float v[8], ss = 0.f;
#pragma unroll
            for (int cc = 0; cc < 8; cc++) {
                v[cc] = src[l + 32 * cc];
                ss = fmaf(v[cc], v[cc], ss);
            }
#pragma unroll
            for (int off = 16; off; off >>= 1) ss += __shfl_xor_sync(0xffffffffu, ss, off);
            float sc = 1.f / fmaxf(sqrtf(ss), 1e-12f);
#pragma unroll
            for (int cc = 0; cc < 8; cc++) vbuf[w][l + 32 * cc] = v[cc] * sc;
            __syncwarp();
            float dot = 0.f;
            const float* qrow = &qs[l * 257];
#pragma unroll 8
            for (int d = 0; d < 256; d++) dot = fmaf(qrow[d], vbuf[w][d], dot);
            accv += expf(dot * 10.f);
            __syncwarp();
        }
    }
    warpP[w][l] = accv;
    __syncthreads();
    if (w == 0) {
        float p = 0.f;
#pragma unroll
        for (int ww = 0; ww < 8; ww++) p += warpP[ww][l];
        g_dacc[(task * 4 + sg) * 32 + l] = p;
    }
}

// ---------------- final: pair finalize + local + global loss -----------------
__global__ __launch_bounds__(256) void k_final(float* __restrict__ out, int out_size) {
    __shared__ float scratch[34];
    __shared__ float qf[4][257], qb[4][257];
    __shared__ float cf[4], cb[4];
    __shared__ float pfv[4], pbv[4], nfv[4], nbv[4];
    __shared__ float sbl[8];
    __shared__ int sinc[8];
    int tid = threadIdx.x;

    {
        int task = tid >> 5, l = tid & 31;
        float p = g_dacc[(task * 4 + 0) * 32 + l] + g_dacc[(task * 4 + 1) * 32 + l];
        float n = g_dacc[(task * 4 + 2) * 32 + l] + g_dacc[(task * 4 + 3) * 32 + l];
        bool inc = (g_cA[task] >= 1) && (g_cB[task] >= 1);
        if (!inc) p += 1.f;
        float per = -logf(p / (p + n + 1e-8f));
        float af = g_aflag[task * 32 + l];
        float ws = per * af, as = af;
#pragma unroll
        for (int off = 16; off; off >>= 1) {
            ws += __shfl_down_sync(0xffffffffu, ws, off);
            as += __shfl_down_sync(0xffffffffu, as, off);
        }
        if (l == 0) {
            sbl[task] = inc ? (ws / fmaxf(as, 1.f)) : 0.f;
            sinc[task] = inc ? 1 : 0;
        }
    }
    __syncthreads();

    for (int b = 0; b < 4; b++) {
        float c1 = 0.f, c0 = 0.f;
        for (int i = tid; i < HW; i += 256) {
            c1 += (float)g_m1[b * HW + i];
            c0 += (float)g_m0[b * HW + i];
        }
        float s1 = blk_sum(scratch, c1, tid);
        float s0 = blk_sum(scratch, c0, tid);
        if (tid == 0) { cf[b] = s1; cb[b] = s0; }
    }
    __syncthreads();

    for (int b = 0; b < 4; b++) {
        float mf = g_mfg[b * Dm + tid] / fmaxf(cf[b], 1.f);
        float mb_ = g_mbg[b * Dm + tid] / fmaxf(cb[b], 1.f);
        float ssf = blk_sum(scratch, mf * mf, tid);
        qf[b][tid] = mf / fmaxf(sqrtf(ssf), 1e-12f);
        float ssb = blk_sum(scratch, mb_ * mb_, tid);
        qb[b][tid] = mb_ / fmaxf(sqrtf(ssb), 1e-12f);
    }
    __syncthreads();

    for (int b = 0; b < 4; b++) {
        float d1 = blk_sum(scratch, qf[b][tid] * qf[b][tid], tid);
        float d2 = blk_sum(scratch, qb[b][tid] * qb[b][tid], tid);
        if (tid == 0) {
            pfv[b] = expf(d1 * 10.f);
            pbv[b] = expf(d2 * 10.f);
            nfv[b] = 0.f;
            nbv[b] = 0.f;
        }
        __syncthreads();
    }
    for (int b = 0; b < 4; b++) {
        for (int j = 0; j <= b; j++) {
            float dqbqf = blk_sum(scratch, qb[j][tid] * qf[b][tid], tid);
            float dqfqb = blk_sum(scratch, qf[j][tid] * qb[b][tid], tid);
            if (tid == 0) {
                bool vgj = (cf[j] >= 1.f) && (cb[j] >= 1.f);
                if (vgj) {
                    nfv[b] += expf(dqbqf * 10.f);
                    nbv[b] += expf(dqfqb * 10.f);
                }
            }
            __syncthreads();
        }
    }

    if (tid == 0) {
        float lsum = 0.f;
        int icnt = 0;
        for (int t = 0; t < 8; t++) {
            lsum += sbl[t];
            icnt += sinc[t];
        }
        float l_local = lsum / (float)max(icnt, 1);
        float gs = 0.f;
        int vcnt = 0;
        for (int b = 0; b < 4; b++) {
            bool vg = (cf[b] >= 1.f) && (cb[b] >= 1.f);
            if (vg) {
                float lg = -logf(pfv[b] / (pfv[b] + nfv[b] + 1e-8f)) -
                           logf(pbv[b] / (pbv[b] + nbv[b] + 1e-8f));
                gs += lg;
                vcnt++;
            }
        }
        float l_global = gs / (float)max(vcnt, 1);
        if (out_size > 0) out[0] = l_local + 0.5f * l_global;
        if (out_size > 1) out[1] = l_local;
        if (out_size > 2) out[2] = l_global;
    }
}

// ---------------- launch ------------------------------------------------------
extern "C" void kernel_launch(void* const* d_in, const int* in_sizes, int n_in, void* d_out,
                              int out_size) {
    const float* feat = (const float*)d_in[0];
    const int* labels = (const int*)d_in[1];
    const float* prob_ori = (const float*)d_in[2];
    const float* prob_aug = (const float*)d_in[3];
    const float* unc = (const float*)d_in[4];
    const float* r_anc = (const float*)d_in[5];
    const float* r_pos = (const float*)d_in[6];
    const float* r_neg = (const float*)d_in[7];
    const float* w1 = (const float*)d_in[8];
    const float* b1 = (const float*)d_in[9];
    const float* gamma = (const float*)d_in[10];
    const float* beta = (const float*)d_in[11];
    const float* w2 = (const float*)d_in[12];
    const float* b2 = (const float*)d_in[13];

    cudaFuncSetAttribute(k_gemm_mma<false>, cudaFuncAttributeMaxDynamicSharedMemorySize,
                         GEMM_SMEM);
    cudaFuncSetAttribute(k_gemm_mma<true>, cudaFuncAttributeMaxDynamicSharedMemorySize,
                         GEMM_SMEM);

    k_masks<<<(Bm * HW + 255) / 256, 256>>>(prob_ori, prob_aug, unc, labels);
    k_splitw<<<dim3(Dm * Dm / 2 / 256, 2), 256>>>(w1, w2);
    k_split_feat<<<dim3(HW / 64, Dm / 64, Bm), 256>>>(feat);
    k_gemm_mma<false><<<8 + NBLK * 2 * Bm, 256, GEMM_SMEM>>>(b1, unc, r_anc, r_pos, r_neg);
    k_finstats<<<Dm, 128>>>(gamma, beta);
    k_bnsplit<<<Bm * HW / 8, 256>>>();
    k_gemm_mma<true><<<NBLK * 2 * Bm, 256, GEMM_SMEM>>>(b2, nullptr, nullptr, nullptr, nullptr);
    k_finproto<<<dim3(Dm, Bm), 128>>>();
    k_dot<<<dim3(4, 8), 256>>>();
    k_final<<<1, 256>>>((float*)d_out, out_size);
}